// round 4
// baseline (speedup 1.0000x reference)
#include <cuda_runtime.h>
#include <math.h>

// Problem constants
#define BATCH 2
#define SEQ   2048
#define DMODEL 1024
#define NHEAD 16
#define DK    64
#define NBH   (BATCH*NHEAD)

// -------- scratch (no cudaMalloc allowed) --------
__device__ float g_Q[NBH * SEQ * DK];      // [b,h,s,d]
__device__ float g_K[NBH * SEQ * DK];
__device__ float g_V[NBH * SEQ * DK];
__device__ float g_attn[BATCH * SEQ * DMODEL]; // [b,s, h*dk]
__device__ float g_cos[SEQ * DK];
__device__ float g_sin[SEQ * DK];

// ============================================================
// Kernel 0: RoPE tables (tiny; double precision for the freq so we are
// at least as accurate as the fp32 reference).
// ============================================================
__global__ void rope_table_kernel(const int* __restrict__ tp) {
    int s = blockIdx.x;      // 0..SEQ-1
    int d = threadIdx.x;     // 0..63
    int k = d >> 1;
    double freq = exp(-(double)(2 * k) / 64.0 * log(10000.0));
    double ang = (double)tp[s] * freq;
    g_cos[s * DK + d] = (float)cos(ang);
    g_sin[s * DK + d] = (float)sin(ang);
}

// ============================================================
// Kernel 1: fused QKV GEMM (+ RoPE + head-transpose epilogue)
// C[m, e] = sum_k x[m,k] * W[e,k],  M=4096, N=3072, K=1024 (NT gemm)
// tile 64x64, BK=32, 256 threads, 4x4 per thread
// ============================================================
__global__ __launch_bounds__(256) void qkv_gemm_kernel(
    const float* __restrict__ x,
    const float* __restrict__ WQ,
    const float* __restrict__ WK,
    const float* __restrict__ WV)
{
    __shared__ float As[32][68];   // [k][m]
    __shared__ float Bs[32][68];   // [k][n]

    const int m0 = blockIdx.y * 64;
    const int e0 = blockIdx.x * 64;
    const int sect = e0 >> 10;                       // 0:Q 1:K 2:V (tile never crosses)
    const float* Wp = (sect == 0 ? WQ : (sect == 1 ? WK : WV)) + (size_t)(e0 & 1023) * DMODEL;
    const float* Ap = x + (size_t)m0 * DMODEL;

    const int tid = threadIdx.x;
    const int tx = tid & 15, ty = tid >> 4;
    const int lrow = tid >> 3;          // 0..31
    const int lc4  = (tid & 7) * 4;     // 0..28

    float acc[4][4] = {};

    for (int kb = 0; kb < DMODEL; kb += 32) {
        float4 a0 = *(const float4*)(Ap + (size_t)lrow * DMODEL + kb + lc4);
        float4 a1 = *(const float4*)(Ap + (size_t)(lrow + 32) * DMODEL + kb + lc4);
        float4 b0 = *(const float4*)(Wp + (size_t)lrow * DMODEL + kb + lc4);
        float4 b1 = *(const float4*)(Wp + (size_t)(lrow + 32) * DMODEL + kb + lc4);
        __syncthreads();
        As[lc4 + 0][lrow] = a0.x; As[lc4 + 1][lrow] = a0.y;
        As[lc4 + 2][lrow] = a0.z; As[lc4 + 3][lrow] = a0.w;
        As[lc4 + 0][lrow + 32] = a1.x; As[lc4 + 1][lrow + 32] = a1.y;
        As[lc4 + 2][lrow + 32] = a1.z; As[lc4 + 3][lrow + 32] = a1.w;
        Bs[lc4 + 0][lrow] = b0.x; Bs[lc4 + 1][lrow] = b0.y;
        Bs[lc4 + 2][lrow] = b0.z; Bs[lc4 + 3][lrow] = b0.w;
        Bs[lc4 + 0][lrow + 32] = b1.x; Bs[lc4 + 1][lrow + 32] = b1.y;
        Bs[lc4 + 2][lrow + 32] = b1.z; Bs[lc4 + 3][lrow + 32] = b1.w;
        __syncthreads();
        #pragma unroll
        for (int k = 0; k < 32; k++) {
            const float4 av = *(const float4*)&As[k][ty * 4];
            const float4 bv = *(const float4*)&Bs[k][tx * 4];
            acc[0][0] += av.x * bv.x; acc[0][1] += av.x * bv.y;
            acc[0][2] += av.x * bv.z; acc[0][3] += av.x * bv.w;
            acc[1][0] += av.y * bv.x; acc[1][1] += av.y * bv.y;
            acc[1][2] += av.y * bv.z; acc[1][3] += av.y * bv.w;
            acc[2][0] += av.z * bv.x; acc[2][1] += av.z * bv.y;
            acc[2][2] += av.z * bv.z; acc[2][3] += av.z * bv.w;
            acc[3][0] += av.w * bv.x; acc[3][1] += av.w * bv.y;
            acc[3][2] += av.w * bv.z; acc[3][3] += av.w * bv.w;
        }
    }

    // epilogue: RoPE (Q,K) + scatter to [b,h,s,d]
    float* dst = (sect == 0) ? g_Q : ((sect == 1) ? g_K : g_V);
    const int n_base = e0 + tx * 4;
    const int ec = n_base & 1023;
    const int h = ec >> 6;
    const int d0 = ec & 63;          // multiple of 4, pairs intra-thread
    #pragma unroll
    for (int i = 0; i < 4; i++) {
        const int row = m0 + ty * 4 + i;          // global bs index
        const int b = row >> 11;
        const int srow = row & (SEQ - 1);
        const size_t oidx = (((size_t)(b * NHEAD + h)) * SEQ + srow) * DK + d0;
        if (sect < 2) {
            #pragma unroll
            for (int jp = 0; jp < 2; jp++) {
                const int d = d0 + jp * 2;
                const float cs = g_cos[srow * DK + d];
                const float sn = g_sin[srow * DK + d];
                const float c0 = acc[i][jp * 2 + 0];
                const float c1 = acc[i][jp * 2 + 1];
                dst[oidx + jp * 2 + 0] = c0 * cs - c1 * sn;
                dst[oidx + jp * 2 + 1] = c1 * cs + c0 * sn;
            }
        } else {
            float4 v = make_float4(acc[i][0], acc[i][1], acc[i][2], acc[i][3]);
            *(float4*)(dst + oidx) = v;
        }
    }
}

// ============================================================
// Kernel 2: causal flash attention, fp32.
// grid (SEQ/64, NBH), 64 threads; thread t owns query row q0+t.
// LPT schedule: heaviest query tiles (largest qt) launch FIRST so the
// causal-triangle work imbalance doesn't sit in the last wave.
// ============================================================
__global__ __launch_bounds__(64) void attn_kernel()
{
    __shared__ float ks[64][64];
    __shared__ float vs[64][64];
    __shared__ float ss[64][64];    // [j][t] per-thread score column

    const int qt = gridDim.x - 1 - blockIdx.x;   // reversed: heavy tiles first
    const int bh = blockIdx.y;
    const int t  = threadIdx.x;
    const int q0 = qt * 64;
    const int qg = q0 + t;

    const float* Qb = g_Q + (size_t)bh * SEQ * DK;
    const float* Kb = g_K + (size_t)bh * SEQ * DK;
    const float* Vb = g_V + (size_t)bh * SEQ * DK;

    // stage Q tile through ks, then copy own row to registers
    #pragma unroll 8
    for (int i = 0; i < 64; i++) ks[i][t] = Qb[(size_t)(q0 + i) * DK + t];
    __syncthreads();
    float q[64];
    #pragma unroll
    for (int dc = 0; dc < 16; dc++) {
        const float4 t4 = *(const float4*)&ks[t][dc * 4];
        q[dc * 4 + 0] = t4.x; q[dc * 4 + 1] = t4.y;
        q[dc * 4 + 2] = t4.z; q[dc * 4 + 3] = t4.w;
    }

    float o[64];
    #pragma unroll
    for (int d = 0; d < 64; d++) o[d] = 0.f;
    float m = -INFINITY, l = 0.f;

    for (int kt = 0; kt <= qt; kt++) {
        const int k0 = kt * 64;
        __syncthreads();   // prior tile fully consumed (also covers Q staging)
        #pragma unroll 8
        for (int i = 0; i < 64; i++) {
            ks[i][t] = Kb[(size_t)(k0 + i) * DK + t];
            vs[i][t] = Vb[(size_t)(k0 + i) * DK + t];
        }
        __syncthreads();

        // pass 1: scores + mask + running tile max
        const int lim = qg - k0;       // j <= lim is valid (>=63 off-diagonal)
        float mt = -INFINITY;
        for (int j = 0; j < 64; j++) {
            float a0 = 0.f, a1 = 0.f, a2 = 0.f, a3 = 0.f;
            #pragma unroll
            for (int dc = 0; dc < 16; dc++) {
                const float4 k4 = *(const float4*)&ks[j][dc * 4];  // broadcast
                a0 += q[dc * 4 + 0] * k4.x;
                a1 += q[dc * 4 + 1] * k4.y;
                a2 += q[dc * 4 + 2] * k4.z;
                a3 += q[dc * 4 + 3] * k4.w;
            }
            float sc = (a0 + a1) + (a2 + a3);
            sc = (j <= lim) ? sc * 0.125f : -INFINITY;
            mt = fmaxf(mt, sc);
            ss[j][t] = sc;
        }

        // online-softmax rescale
        const float mn = fmaxf(m, mt);
        const float alpha = __expf(m - mn);   // 0 on first tile (m=-inf)
        m = mn;
        l *= alpha;
        #pragma unroll
        for (int d = 0; d < 64; d++) o[d] *= alpha;

        // pass 2: P*V accumulate
        for (int j = 0; j < 64; j++) {
            const float p = __expf(ss[j][t] - mn);   // masked -> 0
            l += p;
            #pragma unroll
            for (int dc = 0; dc < 16; dc++) {
                const float4 v4 = *(const float4*)&vs[j][dc * 4]; // broadcast
                o[dc * 4 + 0] += p * v4.x;
                o[dc * 4 + 1] += p * v4.y;
                o[dc * 4 + 2] += p * v4.z;
                o[dc * 4 + 3] += p * v4.w;
            }
        }
    }

    // write to [b, s, h*dk]
    const float inv_l = 1.0f / l;
    const int b = bh >> 4;
    const int h = bh & 15;
    float* dst = g_attn + ((size_t)b * SEQ + qg) * DMODEL + h * DK;
    #pragma unroll
    for (int dc = 0; dc < 16; dc++) {
        float4 v = make_float4(o[dc * 4 + 0] * inv_l, o[dc * 4 + 1] * inv_l,
                               o[dc * 4 + 2] * inv_l, o[dc * 4 + 3] * inv_l);
        *(float4*)(dst + dc * 4) = v;
    }
}

// ============================================================
// Kernel 3: output projection GEMM: out[m,e] = sum_k attn[m,k] * WO[e,k]
// M=4096, N=1024, K=1024. Same tiling as kernel 1.
// ============================================================
__global__ __launch_bounds__(256) void out_gemm_kernel(
    const float* __restrict__ WO, float* __restrict__ out)
{
    __shared__ float As[32][68];
    __shared__ float Bs[32][68];

    const int m0 = blockIdx.y * 64;
    const int e0 = blockIdx.x * 64;
    const float* Ap = g_attn + (size_t)m0 * DMODEL;
    const float* Wp = WO + (size_t)e0 * DMODEL;

    const int tid = threadIdx.x;
    const int tx = tid & 15, ty = tid >> 4;
    const int lrow = tid >> 3;
    const int lc4  = (tid & 7) * 4;

    float acc[4][4] = {};

    for (int kb = 0; kb < DMODEL; kb += 32) {
        float4 a0 = *(const float4*)(Ap + (size_t)lrow * DMODEL + kb + lc4);
        float4 a1 = *(const float4*)(Ap + (size_t)(lrow + 32) * DMODEL + kb + lc4);
        float4 b0 = *(const float4*)(Wp + (size_t)lrow * DMODEL + kb + lc4);
        float4 b1 = *(const float4*)(Wp + (size_t)(lrow + 32) * DMODEL + kb + lc4);
        __syncthreads();
        As[lc4 + 0][lrow] = a0.x; As[lc4 + 1][lrow] = a0.y;
        As[lc4 + 2][lrow] = a0.z; As[lc4 + 3][lrow] = a0.w;
        As[lc4 + 0][lrow + 32] = a1.x; As[lc4 + 1][lrow + 32] = a1.y;
        As[lc4 + 2][lrow + 32] = a1.z; As[lc4 + 3][lrow + 32] = a1.w;
        Bs[lc4 + 0][lrow] = b0.x; Bs[lc4 + 1][lrow] = b0.y;
        Bs[lc4 + 2][lrow] = b0.z; Bs[lc4 + 3][lrow] = b0.w;
        Bs[lc4 + 0][lrow + 32] = b1.x; Bs[lc4 + 1][lrow + 32] = b1.y;
        Bs[lc4 + 2][lrow + 32] = b1.z; Bs[lc4 + 3][lrow + 32] = b1.w;
        __syncthreads();
        #pragma unroll
        for (int k = 0; k < 32; k++) {
            const float4 av = *(const float4*)&As[k][ty * 4];
            const float4 bv = *(const float4*)&Bs[k][tx * 4];
            acc[0][0] += av.x * bv.x; acc[0][1] += av.x * bv.y;
            acc[0][2] += av.x * bv.z; acc[0][3] += av.x * bv.w;
            acc[1][0] += av.y * bv.x; acc[1][1] += av.y * bv.y;
            acc[1][2] += av.y * bv.z; acc[1][3] += av.y * bv.w;
            acc[2][0] += av.z * bv.x; acc[2][1] += av.z * bv.y;
            acc[2][2] += av.z * bv.z; acc[2][3] += av.z * bv.w;
            acc[3][0] += av.w * bv.x; acc[3][1] += av.w * bv.y;
            acc[3][2] += av.w * bv.z; acc[3][3] += av.w * bv.w;
        }
    }

    #pragma unroll
    for (int i = 0; i < 4; i++) {
        const int row = m0 + ty * 4 + i;
        float4 v = make_float4(acc[i][0], acc[i][1], acc[i][2], acc[i][3]);
        *(float4*)(out + (size_t)row * DMODEL + e0 + tx * 4) = v;
    }
}

// ============================================================
extern "C" void kernel_launch(void* const* d_in, const int* in_sizes, int n_in,
                              void* d_out, int out_size)
{
    const float* x  = (const float*)d_in[0];
    const float* WQ = (const float*)d_in[1];
    const float* WK = (const float*)d_in[2];
    const float* WV = (const float*)d_in[3];
    const float* WO = (const float*)d_in[4];
    const int*   tp = (const int*)d_in[5];
    float* out = (float*)d_out;

    rope_table_kernel<<<SEQ, DK>>>(tp);
    qkv_gemm_kernel<<<dim3(3 * DMODEL / 64, BATCH * SEQ / 64), 256>>>(x, WQ, WK, WV);
    attn_kernel<<<dim3(SEQ / 64, NBH), 64>>>();
    out_gemm_kernel<<<dim3(DMODEL / 64, BATCH * SEQ / 64), 256>>>(WO, out);
}

// round 6
// speedup vs baseline: 1.1747x; 1.1747x over previous
#include <cuda_runtime.h>
#include <math.h>

// Problem constants
#define BATCH 2
#define SEQ   2048
#define DMODEL 1024
#define NHEAD 16
#define DK    64
#define NBH   (BATCH*NHEAD)

// -------- scratch (no cudaMalloc allowed) --------
__device__ float g_Q[NBH * SEQ * DK];      // [b,h,s,d]
__device__ float g_K[NBH * SEQ * DK];
__device__ float g_V[NBH * SEQ * DK];
__device__ float g_attn[BATCH * SEQ * DMODEL]; // [b,s, h*dk]
__device__ float g_cos[SEQ * DK];
__device__ float g_sin[SEQ * DK];

// ============================================================
// Kernel 0: RoPE tables
// ============================================================
__global__ void rope_table_kernel(const int* __restrict__ tp) {
    int s = blockIdx.x;
    int d = threadIdx.x;
    int k = d >> 1;
    double freq = exp(-(double)(2 * k) / 64.0 * log(10000.0));
    double ang = (double)tp[s] * freq;
    g_cos[s * DK + d] = (float)cos(ang);
    g_sin[s * DK + d] = (float)sin(ang);
}

// ============================================================
// tf32 helpers (3xTF32 split: x = hi + lo, products hi*hi+hi*lo+lo*hi)
// ============================================================
__device__ __forceinline__ float tf32_rna(float x) {
    unsigned u;
    asm("cvt.rna.tf32.f32 %0, %1;" : "=r"(u) : "f"(x));
    return __uint_as_float(u);
}
__device__ __forceinline__ void split4(float4 v, float4& h, float4& l) {
    h.x = tf32_rna(v.x); l.x = tf32_rna(v.x - h.x);
    h.y = tf32_rna(v.y); l.y = tf32_rna(v.y - h.y);
    h.z = tf32_rna(v.z); l.z = tf32_rna(v.z - h.z);
    h.w = tf32_rna(v.w); l.w = tf32_rna(v.w - h.w);
}
__device__ __forceinline__ void mma_tf32(float c[4], const unsigned a[4], const unsigned b[2]) {
    asm volatile(
        "mma.sync.aligned.m16n8k8.row.col.f32.tf32.tf32.f32 "
        "{%0,%1,%2,%3}, {%4,%5,%6,%7}, {%8,%9}, {%0,%1,%2,%3};"
        : "+f"(c[0]), "+f"(c[1]), "+f"(c[2]), "+f"(c[3])
        : "r"(a[0]), "r"(a[1]), "r"(a[2]), "r"(a[3]), "r"(b[0]), "r"(b[1]));
}
__device__ __forceinline__ unsigned fu(float x) { return __float_as_uint(x); }

// Shared-mem layout constants for the MMA GEMMs
// CTA tile 128(M) x 64(N), BK=16. 256 threads = 8 warps (4 x 2), warp 32x32.
// smem stride 20 words -> conflict-free fragment reads (20*g + t distinct banks).
#define GS 20
#define SM_A_HI 0
#define SM_A_LO (128*GS)
#define SM_B_HI (256*GS)
#define SM_B_LO (256*GS + 64*GS)
#define SM_TOT  (256*GS + 128*GS)   // 7680 floats = 30720 B

// ============================================================
// Shared GEMM mainloop: C[m,n] = sum_k A[m,k]*B[n,k]  (both K-contiguous)
// ============================================================
__device__ __forceinline__ void mma_mainloop(
    const float* __restrict__ Ap, const float* __restrict__ Bp,
    float* sm, float c[2][4][4])
{
    const int tid = threadIdx.x;
    const int lane = tid & 31;
    const int wid = tid >> 5;
    const int wm = (wid & 3) * 32;
    const int wn = (wid >> 2) * 32;
    const int lg = lane >> 2;    // group id 0..7
    const int lt = lane & 3;     // thread-in-group

    const int lrowA = tid >> 2;  // 0..63 (slot0), +64 (slot1)
    const int lq    = tid & 3;   // float4 column quad

    for (int kb = 0; kb < DMODEL; kb += 16) {
        float4 a0v = *(const float4*)(Ap + (size_t)lrowA * DMODEL + kb + lq * 4);
        float4 a1v = *(const float4*)(Ap + (size_t)(lrowA + 64) * DMODEL + kb + lq * 4);
        float4 b0v = *(const float4*)(Bp + (size_t)lrowA * DMODEL + kb + lq * 4);
        float4 h, l;
        __syncthreads();
        split4(a0v, h, l);
        *(float4*)&sm[SM_A_HI + lrowA * GS + lq * 4] = h;
        *(float4*)&sm[SM_A_LO + lrowA * GS + lq * 4] = l;
        split4(a1v, h, l);
        *(float4*)&sm[SM_A_HI + (lrowA + 64) * GS + lq * 4] = h;
        *(float4*)&sm[SM_A_LO + (lrowA + 64) * GS + lq * 4] = l;
        split4(b0v, h, l);
        *(float4*)&sm[SM_B_HI + lrowA * GS + lq * 4] = h;
        *(float4*)&sm[SM_B_LO + lrowA * GS + lq * 4] = l;
        __syncthreads();

        #pragma unroll
        for (int k0 = 0; k0 < 16; k0 += 8) {
            unsigned ah[2][4], al[2][4], bh[4][2], bl[4][2];
            #pragma unroll
            for (int mt = 0; mt < 2; mt++) {
                const int r = wm + mt * 16 + lg;
                ah[mt][0] = fu(sm[SM_A_HI + r * GS + k0 + lt]);
                ah[mt][1] = fu(sm[SM_A_HI + (r + 8) * GS + k0 + lt]);
                ah[mt][2] = fu(sm[SM_A_HI + r * GS + k0 + 4 + lt]);
                ah[mt][3] = fu(sm[SM_A_HI + (r + 8) * GS + k0 + 4 + lt]);
                al[mt][0] = fu(sm[SM_A_LO + r * GS + k0 + lt]);
                al[mt][1] = fu(sm[SM_A_LO + (r + 8) * GS + k0 + lt]);
                al[mt][2] = fu(sm[SM_A_LO + r * GS + k0 + 4 + lt]);
                al[mt][3] = fu(sm[SM_A_LO + (r + 8) * GS + k0 + 4 + lt]);
            }
            #pragma unroll
            for (int nt = 0; nt < 4; nt++) {
                const int cc = wn + nt * 8 + lg;
                bh[nt][0] = fu(sm[SM_B_HI + cc * GS + k0 + lt]);
                bh[nt][1] = fu(sm[SM_B_HI + cc * GS + k0 + 4 + lt]);
                bl[nt][0] = fu(sm[SM_B_LO + cc * GS + k0 + lt]);
                bl[nt][1] = fu(sm[SM_B_LO + cc * GS + k0 + 4 + lt]);
            }
            #pragma unroll
            for (int mt = 0; mt < 2; mt++)
                #pragma unroll
                for (int nt = 0; nt < 4; nt++) {
                    mma_tf32(c[mt][nt], ah[mt], bh[nt]);   // hi*hi
                    mma_tf32(c[mt][nt], ah[mt], bl[nt]);   // hi*lo
                    mma_tf32(c[mt][nt], al[mt], bh[nt]);   // lo*hi
                }
        }
    }
}

// ============================================================
// Kernel 1: QKV projection via 3xTF32 tensor-core MMA (+RoPE epilogue)
// grid (3072/64, 4096/128), 256 threads
// ============================================================
__global__ __launch_bounds__(256, 2) void qkv_mma_kernel(
    const float* __restrict__ x,
    const float* __restrict__ WQ,
    const float* __restrict__ WK,
    const float* __restrict__ WV)
{
    __shared__ float sm[SM_TOT];
    const int m0 = blockIdx.y * 128;
    const int e0 = blockIdx.x * 64;
    const int sect = e0 >> 10;                // 0:Q 1:K 2:V
    const float* Wp = (sect == 0 ? WQ : (sect == 1 ? WK : WV)) + (size_t)(e0 & 1023) * DMODEL;
    const float* Ap = x + (size_t)m0 * DMODEL;

    float c[2][4][4] = {};
    mma_mainloop(Ap, Wp, sm, c);

    // epilogue: RoPE (Q,K) + scatter to [b,h,s,d]
    const int lane = threadIdx.x & 31;
    const int wid = threadIdx.x >> 5;
    const int wm = (wid & 3) * 32;
    const int wn = (wid >> 2) * 32;
    const int lg = lane >> 2, lt = lane & 3;
    float* dst = (sect == 0) ? g_Q : ((sect == 1) ? g_K : g_V);

    #pragma unroll
    for (int mt = 0; mt < 2; mt++) {
        #pragma unroll
        for (int nt = 0; nt < 4; nt++) {
            const int col = e0 + wn + nt * 8 + 2 * lt;     // even
            const int ec = col & 1023;
            const int h = ec >> 6;
            const int d = ec & 63;                          // even
            #pragma unroll
            for (int half = 0; half < 2; half++) {
                const int row = m0 + wm + mt * 16 + lg + half * 8;
                const float v0 = c[mt][nt][half * 2 + 0];
                const float v1 = c[mt][nt][half * 2 + 1];
                const int b = row >> 11;
                const int srow = row & (SEQ - 1);
                const size_t oidx = (((size_t)(b * NHEAD + h)) * SEQ + srow) * DK + d;
                float2 o;
                if (sect < 2) {
                    const float cs = g_cos[srow * DK + d];
                    const float sn = g_sin[srow * DK + d];
                    o.x = v0 * cs - v1 * sn;
                    o.y = v1 * cs + v0 * sn;
                } else {
                    o.x = v0; o.y = v1;
                }
                *(float2*)(dst + oidx) = o;
            }
        }
    }
}

// ============================================================
// Kernel 3: output projection via 3xTF32 MMA
// grid (1024/64, 4096/128), 256 threads
// ============================================================
__global__ __launch_bounds__(256, 2) void out_mma_kernel(
    const float* __restrict__ WO, float* __restrict__ out)
{
    __shared__ float sm[SM_TOT];
    const int m0 = blockIdx.y * 128;
    const int e0 = blockIdx.x * 64;
    const float* Ap = g_attn + (size_t)m0 * DMODEL;
    const float* Wp = WO + (size_t)e0 * DMODEL;

    float c[2][4][4] = {};
    mma_mainloop(Ap, Wp, sm, c);

    const int lane = threadIdx.x & 31;
    const int wid = threadIdx.x >> 5;
    const int wm = (wid & 3) * 32;
    const int wn = (wid >> 2) * 32;
    const int lg = lane >> 2, lt = lane & 3;

    #pragma unroll
    for (int mt = 0; mt < 2; mt++) {
        #pragma unroll
        for (int nt = 0; nt < 4; nt++) {
            const int col = e0 + wn + nt * 8 + 2 * lt;
            #pragma unroll
            for (int half = 0; half < 2; half++) {
                const int row = m0 + wm + mt * 16 + lg + half * 8;
                float2 o;
                o.x = c[mt][nt][half * 2 + 0];
                o.y = c[mt][nt][half * 2 + 1];
                *(float2*)(out + (size_t)row * DMODEL + col) = o;
            }
        }
    }
}

// ============================================================
// Kernel 2: causal flash attention, fp32 (unchanged; LPT schedule).
// ============================================================
__global__ __launch_bounds__(64) void attn_kernel()
{
    __shared__ float ks[64][64];
    __shared__ float vs[64][64];
    __shared__ float ss[64][64];    // [j][t] per-thread score column

    const int qt = gridDim.x - 1 - blockIdx.x;   // reversed: heavy tiles first
    const int bh = blockIdx.y;
    const int t  = threadIdx.x;
    const int q0 = qt * 64;
    const int qg = q0 + t;

    const float* Qb = g_Q + (size_t)bh * SEQ * DK;
    const float* Kb = g_K + (size_t)bh * SEQ * DK;
    const float* Vb = g_V + (size_t)bh * SEQ * DK;

    #pragma unroll 8
    for (int i = 0; i < 64; i++) ks[i][t] = Qb[(size_t)(q0 + i) * DK + t];
    __syncthreads();
    float q[64];
    #pragma unroll
    for (int dc = 0; dc < 16; dc++) {
        const float4 t4 = *(const float4*)&ks[t][dc * 4];
        q[dc * 4 + 0] = t4.x; q[dc * 4 + 1] = t4.y;
        q[dc * 4 + 2] = t4.z; q[dc * 4 + 3] = t4.w;
    }

    float o[64];
    #pragma unroll
    for (int d = 0; d < 64; d++) o[d] = 0.f;
    float m = -INFINITY, l = 0.f;

    for (int kt = 0; kt <= qt; kt++) {
        const int k0 = kt * 64;
        __syncthreads();
        #pragma unroll 8
        for (int i = 0; i < 64; i++) {
            ks[i][t] = Kb[(size_t)(k0 + i) * DK + t];
            vs[i][t] = Vb[(size_t)(k0 + i) * DK + t];
        }
        __syncthreads();

        const int lim = qg - k0;
        float mt = -INFINITY;
        for (int j = 0; j < 64; j++) {
            float a0 = 0.f, a1 = 0.f, a2 = 0.f, a3 = 0.f;
            #pragma unroll
            for (int dc = 0; dc < 16; dc++) {
                const float4 k4 = *(const float4*)&ks[j][dc * 4];
                a0 += q[dc * 4 + 0] * k4.x;
                a1 += q[dc * 4 + 1] * k4.y;
                a2 += q[dc * 4 + 2] * k4.z;
                a3 += q[dc * 4 + 3] * k4.w;
            }
            float sc = (a0 + a1) + (a2 + a3);
            sc = (j <= lim) ? sc * 0.125f : -INFINITY;
            mt = fmaxf(mt, sc);
            ss[j][t] = sc;
        }

        const float mn = fmaxf(m, mt);
        const float alpha = __expf(m - mn);
        m = mn;
        l *= alpha;
        #pragma unroll
        for (int d = 0; d < 64; d++) o[d] *= alpha;

        for (int j = 0; j < 64; j++) {
            const float p = __expf(ss[j][t] - mn);
            l += p;
            #pragma unroll
            for (int dc = 0; dc < 16; dc++) {
                const float4 v4 = *(const float4*)&vs[j][dc * 4];
                o[dc * 4 + 0] += p * v4.x;
                o[dc * 4 + 1] += p * v4.y;
                o[dc * 4 + 2] += p * v4.z;
                o[dc * 4 + 3] += p * v4.w;
            }
        }
    }

    const float inv_l = 1.0f / l;
    const int b = bh >> 4;
    const int h = bh & 15;
    float* dst = g_attn + ((size_t)b * SEQ + qg) * DMODEL + h * DK;
    #pragma unroll
    for (int dc = 0; dc < 16; dc++) {
        float4 v = make_float4(o[dc * 4 + 0] * inv_l, o[dc * 4 + 1] * inv_l,
                               o[dc * 4 + 2] * inv_l, o[dc * 4 + 3] * inv_l);
        *(float4*)(dst + dc * 4) = v;
    }
}

// ============================================================
extern "C" void kernel_launch(void* const* d_in, const int* in_sizes, int n_in,
                              void* d_out, int out_size)
{
    const float* x  = (const float*)d_in[0];
    const float* WQ = (const float*)d_in[1];
    const float* WK = (const float*)d_in[2];
    const float* WV = (const float*)d_in[3];
    const float* WO = (const float*)d_in[4];
    const int*   tp = (const int*)d_in[5];
    float* out = (float*)d_out;

    rope_table_kernel<<<SEQ, DK>>>(tp);
    qkv_mma_kernel<<<dim3(3 * DMODEL / 64, BATCH * SEQ / 128), 256>>>(x, WQ, WK, WV);
    attn_kernel<<<dim3(SEQ / 64, NBH), 64>>>();
    out_mma_kernel<<<dim3(DMODEL / 64, BATCH * SEQ / 128), 256>>>(WO, out);
}

// round 7
// speedup vs baseline: 1.6638x; 1.4164x over previous
#include <cuda_runtime.h>
#include <math.h>

// Problem constants
#define BATCH 2
#define SEQ   2048
#define DMODEL 1024
#define NHEAD 16
#define DK    64
#define NBH   (BATCH*NHEAD)

// -------- scratch (no cudaMalloc allowed) --------
__device__ float g_Q[NBH * SEQ * DK];      // [b,h,s,d]
__device__ float g_K[NBH * SEQ * DK];
__device__ float g_V[NBH * SEQ * DK];
__device__ float g_attn[BATCH * SEQ * DMODEL]; // [b,s, h*dk]
__device__ float g_cos[SEQ * DK];
__device__ float g_sin[SEQ * DK];

// ============================================================
// Kernel 0: RoPE tables
// ============================================================
__global__ void rope_table_kernel(const int* __restrict__ tp) {
    int s = blockIdx.x;
    int d = threadIdx.x;
    int k = d >> 1;
    double freq = exp(-(double)(2 * k) / 64.0 * log(10000.0));
    double ang = (double)tp[s] * freq;
    g_cos[s * DK + d] = (float)cos(ang);
    g_sin[s * DK + d] = (float)sin(ang);
}

// ============================================================
// tf32 helpers
// ============================================================
__device__ __forceinline__ float tf32_rna(float x) {
    unsigned u;
    asm("cvt.rna.tf32.f32 %0, %1;" : "=r"(u) : "f"(x));
    return __uint_as_float(u);
}
__device__ __forceinline__ void split4(float4 v, float4& h, float4& l) {
    h.x = tf32_rna(v.x); l.x = tf32_rna(v.x - h.x);
    h.y = tf32_rna(v.y); l.y = tf32_rna(v.y - h.y);
    h.z = tf32_rna(v.z); l.z = tf32_rna(v.z - h.z);
    h.w = tf32_rna(v.w); l.w = tf32_rna(v.w - h.w);
}
__device__ __forceinline__ void mma_tf32(float c[4], const unsigned a[4], const unsigned b[2]) {
    asm volatile(
        "mma.sync.aligned.m16n8k8.row.col.f32.tf32.tf32.f32 "
        "{%0,%1,%2,%3}, {%4,%5,%6,%7}, {%8,%9}, {%0,%1,%2,%3};"
        : "+f"(c[0]), "+f"(c[1]), "+f"(c[2]), "+f"(c[3])
        : "r"(a[0]), "r"(a[1]), "r"(a[2]), "r"(a[3]), "r"(b[0]), "r"(b[1]));
}
__device__ __forceinline__ unsigned fu(float x) { return __float_as_uint(x); }

// Shared-mem layout constants for the MMA GEMMs (unchanged, validated)
#define GS 20
#define SM_A_HI 0
#define SM_A_LO (128*GS)
#define SM_B_HI (256*GS)
#define SM_B_LO (256*GS + 64*GS)
#define SM_TOT  (256*GS + 128*GS)

// ============================================================
// Shared GEMM mainloop: C[m,n] = sum_k A[m,k]*B[n,k]
// ============================================================
__device__ __forceinline__ void mma_mainloop(
    const float* __restrict__ Ap, const float* __restrict__ Bp,
    float* sm, float c[2][4][4])
{
    const int tid = threadIdx.x;
    const int lane = tid & 31;
    const int wid = tid >> 5;
    const int wm = (wid & 3) * 32;
    const int wn = (wid >> 2) * 32;
    const int lg = lane >> 2;
    const int lt = lane & 3;

    const int lrowA = tid >> 2;
    const int lq    = tid & 3;

    for (int kb = 0; kb < DMODEL; kb += 16) {
        float4 a0v = *(const float4*)(Ap + (size_t)lrowA * DMODEL + kb + lq * 4);
        float4 a1v = *(const float4*)(Ap + (size_t)(lrowA + 64) * DMODEL + kb + lq * 4);
        float4 b0v = *(const float4*)(Bp + (size_t)lrowA * DMODEL + kb + lq * 4);
        float4 h, l;
        __syncthreads();
        split4(a0v, h, l);
        *(float4*)&sm[SM_A_HI + lrowA * GS + lq * 4] = h;
        *(float4*)&sm[SM_A_LO + lrowA * GS + lq * 4] = l;
        split4(a1v, h, l);
        *(float4*)&sm[SM_A_HI + (lrowA + 64) * GS + lq * 4] = h;
        *(float4*)&sm[SM_A_LO + (lrowA + 64) * GS + lq * 4] = l;
        split4(b0v, h, l);
        *(float4*)&sm[SM_B_HI + lrowA * GS + lq * 4] = h;
        *(float4*)&sm[SM_B_LO + lrowA * GS + lq * 4] = l;
        __syncthreads();

        #pragma unroll
        for (int k0 = 0; k0 < 16; k0 += 8) {
            unsigned ah[2][4], al[2][4], bhf[4][2], blf[4][2];
            #pragma unroll
            for (int mt = 0; mt < 2; mt++) {
                const int r = wm + mt * 16 + lg;
                ah[mt][0] = fu(sm[SM_A_HI + r * GS + k0 + lt]);
                ah[mt][1] = fu(sm[SM_A_HI + (r + 8) * GS + k0 + lt]);
                ah[mt][2] = fu(sm[SM_A_HI + r * GS + k0 + 4 + lt]);
                ah[mt][3] = fu(sm[SM_A_HI + (r + 8) * GS + k0 + 4 + lt]);
                al[mt][0] = fu(sm[SM_A_LO + r * GS + k0 + lt]);
                al[mt][1] = fu(sm[SM_A_LO + (r + 8) * GS + k0 + lt]);
                al[mt][2] = fu(sm[SM_A_LO + r * GS + k0 + 4 + lt]);
                al[mt][3] = fu(sm[SM_A_LO + (r + 8) * GS + k0 + 4 + lt]);
            }
            #pragma unroll
            for (int nt = 0; nt < 4; nt++) {
                const int cc = wn + nt * 8 + lg;
                bhf[nt][0] = fu(sm[SM_B_HI + cc * GS + k0 + lt]);
                bhf[nt][1] = fu(sm[SM_B_HI + cc * GS + k0 + 4 + lt]);
                blf[nt][0] = fu(sm[SM_B_LO + cc * GS + k0 + lt]);
                blf[nt][1] = fu(sm[SM_B_LO + cc * GS + k0 + 4 + lt]);
            }
            #pragma unroll
            for (int mt = 0; mt < 2; mt++)
                #pragma unroll
                for (int nt = 0; nt < 4; nt++) {
                    mma_tf32(c[mt][nt], ah[mt], bhf[nt]);
                    mma_tf32(c[mt][nt], ah[mt], blf[nt]);
                    mma_tf32(c[mt][nt], al[mt], bhf[nt]);
                }
        }
    }
}

// ============================================================
// Kernel 1: QKV projection via 3xTF32 MMA (+RoPE epilogue)
// ============================================================
__global__ __launch_bounds__(256, 2) void qkv_mma_kernel(
    const float* __restrict__ x,
    const float* __restrict__ WQ,
    const float* __restrict__ WK,
    const float* __restrict__ WV)
{
    __shared__ float sm[SM_TOT];
    const int m0 = blockIdx.y * 128;
    const int e0 = blockIdx.x * 64;
    const int sect = e0 >> 10;
    const float* Wp = (sect == 0 ? WQ : (sect == 1 ? WK : WV)) + (size_t)(e0 & 1023) * DMODEL;
    const float* Ap = x + (size_t)m0 * DMODEL;

    float c[2][4][4] = {};
    mma_mainloop(Ap, Wp, sm, c);

    const int lane = threadIdx.x & 31;
    const int wid = threadIdx.x >> 5;
    const int wm = (wid & 3) * 32;
    const int wn = (wid >> 2) * 32;
    const int lg = lane >> 2, lt = lane & 3;
    float* dst = (sect == 0) ? g_Q : ((sect == 1) ? g_K : g_V);

    #pragma unroll
    for (int mt = 0; mt < 2; mt++) {
        #pragma unroll
        for (int nt = 0; nt < 4; nt++) {
            const int col = e0 + wn + nt * 8 + 2 * lt;
            const int ec = col & 1023;
            const int h = ec >> 6;
            const int d = ec & 63;
            #pragma unroll
            for (int half = 0; half < 2; half++) {
                const int row = m0 + wm + mt * 16 + lg + half * 8;
                const float v0 = c[mt][nt][half * 2 + 0];
                const float v1 = c[mt][nt][half * 2 + 1];
                const int b = row >> 11;
                const int srow = row & (SEQ - 1);
                const size_t oidx = (((size_t)(b * NHEAD + h)) * SEQ + srow) * DK + d;
                float2 o;
                if (sect < 2) {
                    const float cs = g_cos[srow * DK + d];
                    const float sn = g_sin[srow * DK + d];
                    o.x = v0 * cs - v1 * sn;
                    o.y = v1 * cs + v0 * sn;
                } else {
                    o.x = v0; o.y = v1;
                }
                *(float2*)(dst + oidx) = o;
            }
        }
    }
}

// ============================================================
// Kernel 3: output projection via 3xTF32 MMA
// ============================================================
__global__ __launch_bounds__(256, 2) void out_mma_kernel(
    const float* __restrict__ WO, float* __restrict__ out)
{
    __shared__ float sm[SM_TOT];
    const int m0 = blockIdx.y * 128;
    const int e0 = blockIdx.x * 64;
    const float* Ap = g_attn + (size_t)m0 * DMODEL;
    const float* Wp = WO + (size_t)e0 * DMODEL;

    float c[2][4][4] = {};
    mma_mainloop(Ap, Wp, sm, c);

    const int lane = threadIdx.x & 31;
    const int wid = threadIdx.x >> 5;
    const int wm = (wid & 3) * 32;
    const int wn = (wid >> 2) * 32;
    const int lg = lane >> 2, lt = lane & 3;

    #pragma unroll
    for (int mt = 0; mt < 2; mt++) {
        #pragma unroll
        for (int nt = 0; nt < 4; nt++) {
            const int col = e0 + wn + nt * 8 + 2 * lt;
            #pragma unroll
            for (int half = 0; half < 2; half++) {
                const int row = m0 + wm + mt * 16 + lg + half * 8;
                float2 o;
                o.x = c[mt][nt][half * 2 + 0];
                o.y = c[mt][nt][half * 2 + 1];
                *(float2*)(out + (size_t)row * DMODEL + col) = o;
            }
        }
    }
}

// ============================================================
// Kernel 2: causal flash attention via tensor-core MMA.
// 128 threads = 4 warps; warp w owns q rows [q0+16w, q0+16w+16).
// 32-key subtiles. Scores: 3xTF32 (Q hi/lo regs, K hi/lo smem).
// Softmax in registers (shfl over lt quad). PV: single tf32,
// P staged via smem (rna), V transposed in smem (rna).
// ============================================================
#define KST 68   // K smem row stride (banks: 4*lg+lt, conflict-free)
#define VST 36   // V^T / P smem row stride (banks: 4*lg+lt)

__global__ __launch_bounds__(128) void attn_mma_kernel()
{
    __shared__ float s_k[64 * KST];   // kh [0..32*KST), kl [32*KST..); Q staging (64 x KST)
    __shared__ float s_vt[64 * VST];  // V^T (tf32 values): [dim][key]
    __shared__ float s_ps[64 * VST];  // P: [qrow][key]

    const int qt = gridDim.x - 1 - blockIdx.x;   // LPT: heavy tiles first
    const int bh = blockIdx.y;
    const int tid = threadIdx.x;
    const int w = tid >> 5;
    const int lane = tid & 31;
    const int lg = lane >> 2, lt = lane & 3;
    const int q0 = qt * 64;

    const float* Qb = g_Q + (size_t)bh * SEQ * DK;
    const float* Kb = g_K + (size_t)bh * SEQ * DK;
    const float* Vb = g_V + (size_t)bh * SEQ * DK;

    // ---- stage Q tile (pre-scaled by 1/8) ----
    {
        const int row = tid & 63, half = tid >> 6;
        const float* src = Qb + (size_t)(q0 + row) * DK + 32 * half;
        float* dq = s_k + row * KST + 32 * half;
        #pragma unroll
        for (int i = 0; i < 8; i++) {
            float4 v = *(const float4*)(src + 4 * i);
            v.x *= 0.125f; v.y *= 0.125f; v.z *= 0.125f; v.w *= 0.125f;
            *(float4*)(dq + 4 * i) = v;
        }
    }
    __syncthreads();

    // ---- extract Q A-fragments (hi/lo) into registers ----
    unsigned qh[8][4], ql[8][4];
    {
        const int r0 = 16 * w + lg;
        #pragma unroll
        for (int kc = 0; kc < 8; kc++) {
            float f[4];
            f[0] = s_k[r0 * KST + kc * 8 + lt];
            f[1] = s_k[(r0 + 8) * KST + kc * 8 + lt];
            f[2] = s_k[r0 * KST + kc * 8 + 4 + lt];
            f[3] = s_k[(r0 + 8) * KST + kc * 8 + 4 + lt];
            #pragma unroll
            for (int i = 0; i < 4; i++) {
                float hi = tf32_rna(f[i]);
                qh[kc][i] = fu(hi);
                ql[kc][i] = fu(tf32_rna(f[i] - hi));
            }
        }
    }

    float o[8][4];
    #pragma unroll
    for (int nt = 0; nt < 8; nt++)
        #pragma unroll
        for (int i = 0; i < 4; i++) o[nt][i] = 0.f;
    float m0 = -1e30f, m1 = -1e30f, l0 = 0.f, l1 = 0.f;
    const int rg0 = q0 + 16 * w + lg;
    const int rg1 = rg0 + 8;
    const int nsub = 2 * qt + 2;

    for (int s32 = 0; s32 < nsub; s32++) {
        const int k32 = s32 * 32;
        __syncthreads();   // prior S/PV reads of s_k/s_vt complete (also Q frag extraction on iter 0)

        // ---- load K (hi/lo split) and V (transposed, tf32) ----
        {
            const int key = tid & 31, part = tid >> 5;   // dims [16*part, 16*part+16)
            const float* ksrc = Kb + (size_t)(k32 + key) * DK + 16 * part;
            #pragma unroll
            for (int i = 0; i < 4; i++) {
                float4 v = *(const float4*)(ksrc + 4 * i);
                float4 h, l; split4(v, h, l);
                *(float4*)(s_k + key * KST + 16 * part + 4 * i) = h;
                *(float4*)(s_k + 32 * KST + key * KST + 16 * part + 4 * i) = l;
            }
            const float* vsrc = Vb + (size_t)(k32 + key) * DK + 16 * part;
            #pragma unroll
            for (int i = 0; i < 4; i++) {
                float4 v = *(const float4*)(vsrc + 4 * i);
                s_vt[(16 * part + 4 * i + 0) * VST + key] = tf32_rna(v.x);
                s_vt[(16 * part + 4 * i + 1) * VST + key] = tf32_rna(v.y);
                s_vt[(16 * part + 4 * i + 2) * VST + key] = tf32_rna(v.z);
                s_vt[(16 * part + 4 * i + 3) * VST + key] = tf32_rna(v.w);
            }
        }
        __syncthreads();

        const bool active = (k32 <= q0 + 16 * w + 15);
        if (active) {
            // ---- scores S = Q*K^T (3xTF32) ----
            float s[4][4];
            #pragma unroll
            for (int nt = 0; nt < 4; nt++)
                #pragma unroll
                for (int i = 0; i < 4; i++) s[nt][i] = 0.f;
            #pragma unroll
            for (int nt = 0; nt < 4; nt++) {
                const int kr = (nt * 8 + lg) * KST;
                #pragma unroll
                for (int kc = 0; kc < 8; kc++) {
                    unsigned bhf[2], blf[2];
                    bhf[0] = fu(s_k[kr + kc * 8 + lt]);
                    bhf[1] = fu(s_k[kr + kc * 8 + 4 + lt]);
                    blf[0] = fu(s_k[32 * KST + kr + kc * 8 + lt]);
                    blf[1] = fu(s_k[32 * KST + kr + kc * 8 + 4 + lt]);
                    mma_tf32(s[nt], qh[kc], bhf);
                    mma_tf32(s[nt], ql[kc], bhf);
                    mma_tf32(s[nt], qh[kc], blf);
                }
            }
            // ---- causal mask ----
            if (k32 + 31 > rg0) {
                #pragma unroll
                for (int nt = 0; nt < 4; nt++) {
                    const int j = k32 + nt * 8 + 2 * lt;
                    if (j > rg0)     s[nt][0] = -1e30f;
                    if (j + 1 > rg0) s[nt][1] = -1e30f;
                }
            }
            if (k32 + 31 > rg1) {
                #pragma unroll
                for (int nt = 0; nt < 4; nt++) {
                    const int j = k32 + nt * 8 + 2 * lt;
                    if (j > rg1)     s[nt][2] = -1e30f;
                    if (j + 1 > rg1) s[nt][3] = -1e30f;
                }
            }
            // ---- online softmax (rows rg0, rg1) ----
            float mt0 = -1e30f, mt1 = -1e30f;
            #pragma unroll
            for (int nt = 0; nt < 4; nt++) {
                mt0 = fmaxf(mt0, fmaxf(s[nt][0], s[nt][1]));
                mt1 = fmaxf(mt1, fmaxf(s[nt][2], s[nt][3]));
            }
            mt0 = fmaxf(mt0, __shfl_xor_sync(0xffffffffu, mt0, 1));
            mt0 = fmaxf(mt0, __shfl_xor_sync(0xffffffffu, mt0, 2));
            mt1 = fmaxf(mt1, __shfl_xor_sync(0xffffffffu, mt1, 1));
            mt1 = fmaxf(mt1, __shfl_xor_sync(0xffffffffu, mt1, 2));
            const float mn0 = fmaxf(m0, mt0), mn1 = fmaxf(m1, mt1);
            const float a0 = __expf(m0 - mn0), a1 = __expf(m1 - mn1);
            m0 = mn0; m1 = mn1;
            float sum0 = 0.f, sum1 = 0.f;
            #pragma unroll
            for (int nt = 0; nt < 4; nt++) {
                s[nt][0] = __expf(s[nt][0] - mn0);
                s[nt][1] = __expf(s[nt][1] - mn0);
                s[nt][2] = __expf(s[nt][2] - mn1);
                s[nt][3] = __expf(s[nt][3] - mn1);
                sum0 += s[nt][0] + s[nt][1];
                sum1 += s[nt][2] + s[nt][3];
            }
            sum0 += __shfl_xor_sync(0xffffffffu, sum0, 1);
            sum0 += __shfl_xor_sync(0xffffffffu, sum0, 2);
            sum1 += __shfl_xor_sync(0xffffffffu, sum1, 1);
            sum1 += __shfl_xor_sync(0xffffffffu, sum1, 2);
            l0 = l0 * a0 + sum0;
            l1 = l1 * a1 + sum1;
            #pragma unroll
            for (int nt = 0; nt < 8; nt++) {
                o[nt][0] *= a0; o[nt][1] *= a0;
                o[nt][2] *= a1; o[nt][3] *= a1;
            }
            // ---- store P (rna-rounded) to own warp's rows ----
            {
                const int pr0 = (16 * w + lg) * VST;
                const int pr1 = (16 * w + 8 + lg) * VST;
                #pragma unroll
                for (int nt = 0; nt < 4; nt++) {
                    float2 p01 = make_float2(tf32_rna(s[nt][0]), tf32_rna(s[nt][1]));
                    float2 p23 = make_float2(tf32_rna(s[nt][2]), tf32_rna(s[nt][3]));
                    *(float2*)(s_ps + pr0 + nt * 8 + 2 * lt) = p01;
                    *(float2*)(s_ps + pr1 + nt * 8 + 2 * lt) = p23;
                }
            }
            __syncwarp();
            // ---- PV: O += P * V ----
            unsigned pa[4][4];
            #pragma unroll
            for (int kc = 0; kc < 4; kc++) {
                pa[kc][0] = fu(s_ps[(16 * w + lg) * VST + kc * 8 + lt]);
                pa[kc][1] = fu(s_ps[(16 * w + 8 + lg) * VST + kc * 8 + lt]);
                pa[kc][2] = fu(s_ps[(16 * w + lg) * VST + kc * 8 + 4 + lt]);
                pa[kc][3] = fu(s_ps[(16 * w + 8 + lg) * VST + kc * 8 + 4 + lt]);
            }
            #pragma unroll
            for (int nt = 0; nt < 8; nt++) {
                const int vr = (nt * 8 + lg) * VST;
                #pragma unroll
                for (int kc = 0; kc < 4; kc++) {
                    unsigned vb[2];
                    vb[0] = fu(s_vt[vr + kc * 8 + lt]);
                    vb[1] = fu(s_vt[vr + kc * 8 + 4 + lt]);
                    mma_tf32(o[nt], pa[kc], vb);
                }
            }
        }
    }

    // ---- normalize + write [b, s, h*dk] ----
    const float inv0 = 1.0f / l0, inv1 = 1.0f / l1;
    const int b = bh >> 4, h = bh & 15;
    float* dst0 = g_attn + ((size_t)b * SEQ + rg0) * DMODEL + h * DK;
    float* dst1 = g_attn + ((size_t)b * SEQ + rg1) * DMODEL + h * DK;
    #pragma unroll
    for (int nt = 0; nt < 8; nt++) {
        *(float2*)(dst0 + nt * 8 + 2 * lt) = make_float2(o[nt][0] * inv0, o[nt][1] * inv0);
        *(float2*)(dst1 + nt * 8 + 2 * lt) = make_float2(o[nt][2] * inv1, o[nt][3] * inv1);
    }
}

// ============================================================
extern "C" void kernel_launch(void* const* d_in, const int* in_sizes, int n_in,
                              void* d_out, int out_size)
{
    const float* x  = (const float*)d_in[0];
    const float* WQ = (const float*)d_in[1];
    const float* WK = (const float*)d_in[2];
    const float* WV = (const float*)d_in[3];
    const float* WO = (const float*)d_in[4];
    const int*   tp = (const int*)d_in[5];
    float* out = (float*)d_out;

    rope_table_kernel<<<SEQ, DK>>>(tp);
    qkv_mma_kernel<<<dim3(3 * DMODEL / 64, BATCH * SEQ / 128), 256>>>(x, WQ, WK, WV);
    attn_mma_kernel<<<dim3(SEQ / 64, NBH), 128>>>();
    out_mma_kernel<<<dim3(DMODEL / 64, BATCH * SEQ / 128), 256>>>(WO, out);
}

// round 9
// speedup vs baseline: 1.8249x; 1.0968x over previous
#include <cuda_runtime.h>
#include <math.h>

// Problem constants
#define BATCH 2
#define SEQ   2048
#define DMODEL 1024
#define NHEAD 16
#define DK    64
#define NBH   (BATCH*NHEAD)

// -------- scratch (no cudaMalloc allowed) --------
__device__ float g_Q[NBH * SEQ * DK];      // [b,h,s,d]
__device__ float g_K[NBH * SEQ * DK];
__device__ float g_V[NBH * SEQ * DK];
__device__ float g_attn[BATCH * SEQ * DMODEL]; // [b,s, h*dk]
__device__ float g_cos[SEQ * DK];
__device__ float g_sin[SEQ * DK];

// ============================================================
// Kernel 0: RoPE tables
// ============================================================
__global__ void rope_table_kernel(const int* __restrict__ tp) {
    int s = blockIdx.x;
    int d = threadIdx.x;
    int k = d >> 1;
    double freq = exp(-(double)(2 * k) / 64.0 * log(10000.0));
    double ang = (double)tp[s] * freq;
    g_cos[s * DK + d] = (float)cos(ang);
    g_sin[s * DK + d] = (float)sin(ang);
}

// ============================================================
// tf32 helpers
// ============================================================
__device__ __forceinline__ float tf32_rna(float x) {
    unsigned u;
    asm("cvt.rna.tf32.f32 %0, %1;" : "=r"(u) : "f"(x));
    return __uint_as_float(u);
}
__device__ __forceinline__ void split4(float4 v, float4& h, float4& l) {
    h.x = tf32_rna(v.x); l.x = tf32_rna(v.x - h.x);
    h.y = tf32_rna(v.y); l.y = tf32_rna(v.y - h.y);
    h.z = tf32_rna(v.z); l.z = tf32_rna(v.z - h.z);
    h.w = tf32_rna(v.w); l.w = tf32_rna(v.w - h.w);
}
__device__ __forceinline__ void splitu(float x, unsigned& h, unsigned& l) {
    float hf = tf32_rna(x);
    h = __float_as_uint(hf);
    l = __float_as_uint(tf32_rna(x - hf));
}
__device__ __forceinline__ void mma_tf32(float c[4], const unsigned a[4], const unsigned b[2]) {
    asm volatile(
        "mma.sync.aligned.m16n8k8.row.col.f32.tf32.tf32.f32 "
        "{%0,%1,%2,%3}, {%4,%5,%6,%7}, {%8,%9}, {%0,%1,%2,%3};"
        : "+f"(c[0]), "+f"(c[1]), "+f"(c[2]), "+f"(c[3])
        : "r"(a[0]), "r"(a[1]), "r"(a[2]), "r"(a[3]), "r"(b[0]), "r"(b[1]));
}
__device__ __forceinline__ unsigned fu(float x) { return __float_as_uint(x); }

__device__ __forceinline__ void cp16(float* smem, const float* gmem) {
    unsigned saddr = (unsigned)__cvta_generic_to_shared(smem);
    asm volatile("cp.async.ca.shared.global [%0], [%1], 16;" :: "r"(saddr), "l"(gmem) : "memory");
}

// ---- GEMM smem layout: raw fp32, double-buffered ----
// A: 128 rows x GS, B: 64 rows x GS  (16 k-values used per row)
#define GS 20
#define SMA 0
#define SMB (128*GS)
#define BUFSZ (192*GS)          // 3840 floats per stage
#define SM_TOT (2*BUFSZ)        // 7680 floats = 30720 B

// ============================================================
// Pipelined GEMM mainloop: C[m,n] = sum_k A[m,k]*B[n,k]
// cp.async double buffer; hi/lo split at fragment load (3xTF32).
// ============================================================
__device__ __forceinline__ void gemm_issue_copy(
    const float* __restrict__ Ap, const float* __restrict__ Bp,
    int kb, float* buf, int tid)
{
    const int r0 = tid >> 2;          // 0..63
    const int q0 = (tid & 3) * 4;     // 0,4,8,12
    cp16(buf + SMA + r0 * GS + q0, Ap + (size_t)r0 * DMODEL + kb + q0);
    cp16(buf + SMA + (r0 + 64) * GS + q0, Ap + (size_t)(r0 + 64) * DMODEL + kb + q0);
    cp16(buf + SMB + r0 * GS + q0, Bp + (size_t)r0 * DMODEL + kb + q0);
    asm volatile("cp.async.commit_group;" ::: "memory");
}

__device__ __forceinline__ void gemm_compute(
    const float* buf, float c[2][4][4], int wm, int wn, int lg, int lt)
{
    #pragma unroll
    for (int k0 = 0; k0 < 16; k0 += 8) {
        unsigned ah[2][4], al[2][4], bh[4][2], bl[4][2];
        #pragma unroll
        for (int mt = 0; mt < 2; mt++) {
            const int r = wm + mt * 16 + lg;
            splitu(buf[SMA + r * GS + k0 + lt],           ah[mt][0], al[mt][0]);
            splitu(buf[SMA + (r + 8) * GS + k0 + lt],     ah[mt][1], al[mt][1]);
            splitu(buf[SMA + r * GS + k0 + 4 + lt],       ah[mt][2], al[mt][2]);
            splitu(buf[SMA + (r + 8) * GS + k0 + 4 + lt], ah[mt][3], al[mt][3]);
        }
        #pragma unroll
        for (int nt = 0; nt < 4; nt++) {
            const int cc = wn + nt * 8 + lg;
            splitu(buf[SMB + cc * GS + k0 + lt],     bh[nt][0], bl[nt][0]);
            splitu(buf[SMB + cc * GS + k0 + 4 + lt], bh[nt][1], bl[nt][1]);
        }
        #pragma unroll
        for (int mt = 0; mt < 2; mt++)
            #pragma unroll
            for (int nt = 0; nt < 4; nt++) {
                mma_tf32(c[mt][nt], ah[mt], bh[nt]);
                mma_tf32(c[mt][nt], ah[mt], bl[nt]);
                mma_tf32(c[mt][nt], al[mt], bh[nt]);
            }
    }
}

__device__ __forceinline__ void mma_mainloop(
    const float* __restrict__ Ap, const float* __restrict__ Bp,
    float* sm, float c[2][4][4])
{
    const int tid = threadIdx.x;
    const int lane = tid & 31;
    const int wid = tid >> 5;
    const int wm = (wid & 3) * 32;
    const int wn = (wid >> 2) * 32;
    const int lg = lane >> 2;
    const int lt = lane & 3;
    const int NB = DMODEL / 16;   // 64

    gemm_issue_copy(Ap, Bp, 0, sm, tid);
    asm volatile("cp.async.wait_group 0;" ::: "memory");
    __syncthreads();

    for (int i = 0; i < NB; i++) {
        const float* cur = sm + (i & 1) * BUFSZ;
        if (i + 1 < NB)
            gemm_issue_copy(Ap, Bp, (i + 1) * 16, sm + ((i + 1) & 1) * BUFSZ, tid);
        gemm_compute(cur, c, wm, wn, lg, lt);
        if (i + 1 < NB) {
            asm volatile("cp.async.wait_group 0;" ::: "memory");
            __syncthreads();
        }
    }
}

// ============================================================
// Kernel 1: QKV projection via 3xTF32 MMA (+RoPE epilogue)
// ============================================================
__global__ __launch_bounds__(256, 3) void qkv_mma_kernel(
    const float* __restrict__ x,
    const float* __restrict__ WQ,
    const float* __restrict__ WK,
    const float* __restrict__ WV)
{
    __shared__ float sm[SM_TOT];
    const int m0 = blockIdx.y * 128;
    const int e0 = blockIdx.x * 64;
    const int sect = e0 >> 10;
    const float* Wp = (sect == 0 ? WQ : (sect == 1 ? WK : WV)) + (size_t)(e0 & 1023) * DMODEL;
    const float* Ap = x + (size_t)m0 * DMODEL;

    float c[2][4][4] = {};
    mma_mainloop(Ap, Wp, sm, c);

    const int lane = threadIdx.x & 31;
    const int wid = threadIdx.x >> 5;
    const int wm = (wid & 3) * 32;
    const int wn = (wid >> 2) * 32;
    const int lg = lane >> 2, lt = lane & 3;
    float* dst = (sect == 0) ? g_Q : ((sect == 1) ? g_K : g_V);

    #pragma unroll
    for (int mt = 0; mt < 2; mt++) {
        #pragma unroll
        for (int nt = 0; nt < 4; nt++) {
            const int col = e0 + wn + nt * 8 + 2 * lt;
            const int ec = col & 1023;
            const int h = ec >> 6;
            const int d = ec & 63;
            #pragma unroll
            for (int half = 0; half < 2; half++) {
                const int row = m0 + wm + mt * 16 + lg + half * 8;
                const float v0 = c[mt][nt][half * 2 + 0];
                const float v1 = c[mt][nt][half * 2 + 1];
                const int b = row >> 11;
                const int srow = row & (SEQ - 1);
                const size_t oidx = (((size_t)(b * NHEAD + h)) * SEQ + srow) * DK + d;
                float2 o;
                if (sect < 2) {
                    const float cs = g_cos[srow * DK + d];
                    const float sn = g_sin[srow * DK + d];
                    o.x = v0 * cs - v1 * sn;
                    o.y = v1 * cs + v0 * sn;
                } else {
                    o.x = v0; o.y = v1;
                }
                *(float2*)(dst + oidx) = o;
            }
        }
    }
}

// ============================================================
// Kernel 3: output projection via 3xTF32 MMA
// ============================================================
__global__ __launch_bounds__(256, 3) void out_mma_kernel(
    const float* __restrict__ WO, float* __restrict__ out)
{
    __shared__ float sm[SM_TOT];
    const int m0 = blockIdx.y * 128;
    const int e0 = blockIdx.x * 64;
    const float* Ap = g_attn + (size_t)m0 * DMODEL;
    const float* Wp = WO + (size_t)e0 * DMODEL;

    float c[2][4][4] = {};
    mma_mainloop(Ap, Wp, sm, c);

    const int lane = threadIdx.x & 31;
    const int wid = threadIdx.x >> 5;
    const int wm = (wid & 3) * 32;
    const int wn = (wid >> 2) * 32;
    const int lg = lane >> 2, lt = lane & 3;

    #pragma unroll
    for (int mt = 0; mt < 2; mt++) {
        #pragma unroll
        for (int nt = 0; nt < 4; nt++) {
            const int col = e0 + wn + nt * 8 + 2 * lt;
            #pragma unroll
            for (int half = 0; half < 2; half++) {
                const int row = m0 + wm + mt * 16 + lg + half * 8;
                float2 o;
                o.x = c[mt][nt][half * 2 + 0];
                o.y = c[mt][nt][half * 2 + 1];
                *(float2*)(out + (size_t)row * DMODEL + col) = o;
            }
        }
    }
}

// ============================================================
// Kernel 2: causal flash attention via tensor-core MMA (unchanged).
// ============================================================
#define KST 68
#define VST 36

__global__ __launch_bounds__(128) void attn_mma_kernel()
{
    __shared__ float s_k[64 * KST];
    __shared__ float s_vt[64 * VST];
    __shared__ float s_ps[64 * VST];

    const int qt = gridDim.x - 1 - blockIdx.x;
    const int bh = blockIdx.y;
    const int tid = threadIdx.x;
    const int w = tid >> 5;
    const int lane = tid & 31;
    const int lg = lane >> 2, lt = lane & 3;
    const int q0 = qt * 64;

    const float* Qb = g_Q + (size_t)bh * SEQ * DK;
    const float* Kb = g_K + (size_t)bh * SEQ * DK;
    const float* Vb = g_V + (size_t)bh * SEQ * DK;

    {
        const int row = tid & 63, half = tid >> 6;
        const float* src = Qb + (size_t)(q0 + row) * DK + 32 * half;
        float* dq = s_k + row * KST + 32 * half;
        #pragma unroll
        for (int i = 0; i < 8; i++) {
            float4 v = *(const float4*)(src + 4 * i);
            v.x *= 0.125f; v.y *= 0.125f; v.z *= 0.125f; v.w *= 0.125f;
            *(float4*)(dq + 4 * i) = v;
        }
    }
    __syncthreads();

    unsigned qh[8][4], ql[8][4];
    {
        const int r0 = 16 * w + lg;
        #pragma unroll
        for (int kc = 0; kc < 8; kc++) {
            float f[4];
            f[0] = s_k[r0 * KST + kc * 8 + lt];
            f[1] = s_k[(r0 + 8) * KST + kc * 8 + lt];
            f[2] = s_k[r0 * KST + kc * 8 + 4 + lt];
            f[3] = s_k[(r0 + 8) * KST + kc * 8 + 4 + lt];
            #pragma unroll
            for (int i = 0; i < 4; i++) {
                float hi = tf32_rna(f[i]);
                qh[kc][i] = fu(hi);
                ql[kc][i] = fu(tf32_rna(f[i] - hi));
            }
        }
    }

    float o[8][4];
    #pragma unroll
    for (int nt = 0; nt < 8; nt++)
        #pragma unroll
        for (int i = 0; i < 4; i++) o[nt][i] = 0.f;
    float m0 = -1e30f, m1 = -1e30f, l0 = 0.f, l1 = 0.f;
    const int rg0 = q0 + 16 * w + lg;
    const int rg1 = rg0 + 8;
    const int nsub = 2 * qt + 2;

    for (int s32 = 0; s32 < nsub; s32++) {
        const int k32 = s32 * 32;
        __syncthreads();

        {
            const int key = tid & 31, part = tid >> 5;
            const float* ksrc = Kb + (size_t)(k32 + key) * DK + 16 * part;
            #pragma unroll
            for (int i = 0; i < 4; i++) {
                float4 v = *(const float4*)(ksrc + 4 * i);
                float4 h, l; split4(v, h, l);
                *(float4*)(s_k + key * KST + 16 * part + 4 * i) = h;
                *(float4*)(s_k + 32 * KST + key * KST + 16 * part + 4 * i) = l;
            }
            const float* vsrc = Vb + (size_t)(k32 + key) * DK + 16 * part;
            #pragma unroll
            for (int i = 0; i < 4; i++) {
                float4 v = *(const float4*)(vsrc + 4 * i);
                s_vt[(16 * part + 4 * i + 0) * VST + key] = tf32_rna(v.x);
                s_vt[(16 * part + 4 * i + 1) * VST + key] = tf32_rna(v.y);
                s_vt[(16 * part + 4 * i + 2) * VST + key] = tf32_rna(v.z);
                s_vt[(16 * part + 4 * i + 3) * VST + key] = tf32_rna(v.w);
            }
        }
        __syncthreads();

        const bool active = (k32 <= q0 + 16 * w + 15);
        if (active) {
            float s[4][4];
            #pragma unroll
            for (int nt = 0; nt < 4; nt++)
                #pragma unroll
                for (int i = 0; i < 4; i++) s[nt][i] = 0.f;
            #pragma unroll
            for (int nt = 0; nt < 4; nt++) {
                const int kr = (nt * 8 + lg) * KST;
                #pragma unroll
                for (int kc = 0; kc < 8; kc++) {
                    unsigned bhf[2], blf[2];
                    bhf[0] = fu(s_k[kr + kc * 8 + lt]);
                    bhf[1] = fu(s_k[kr + kc * 8 + 4 + lt]);
                    blf[0] = fu(s_k[32 * KST + kr + kc * 8 + lt]);
                    blf[1] = fu(s_k[32 * KST + kr + kc * 8 + 4 + lt]);
                    mma_tf32(s[nt], qh[kc], bhf);
                    mma_tf32(s[nt], ql[kc], bhf);
                    mma_tf32(s[nt], qh[kc], blf);
                }
            }
            if (k32 + 31 > rg0) {
                #pragma unroll
                for (int nt = 0; nt < 4; nt++) {
                    const int j = k32 + nt * 8 + 2 * lt;
                    if (j > rg0)     s[nt][0] = -1e30f;
                    if (j + 1 > rg0) s[nt][1] = -1e30f;
                }
            }
            if (k32 + 31 > rg1) {
                #pragma unroll
                for (int nt = 0; nt < 4; nt++) {
                    const int j = k32 + nt * 8 + 2 * lt;
                    if (j > rg1)     s[nt][2] = -1e30f;
                    if (j + 1 > rg1) s[nt][3] = -1e30f;
                }
            }
            float mt0 = -1e30f, mt1 = -1e30f;
            #pragma unroll
            for (int nt = 0; nt < 4; nt++) {
                mt0 = fmaxf(mt0, fmaxf(s[nt][0], s[nt][1]));
                mt1 = fmaxf(mt1, fmaxf(s[nt][2], s[nt][3]));
            }
            mt0 = fmaxf(mt0, __shfl_xor_sync(0xffffffffu, mt0, 1));
            mt0 = fmaxf(mt0, __shfl_xor_sync(0xffffffffu, mt0, 2));
            mt1 = fmaxf(mt1, __shfl_xor_sync(0xffffffffu, mt1, 1));
            mt1 = fmaxf(mt1, __shfl_xor_sync(0xffffffffu, mt1, 2));
            const float mn0 = fmaxf(m0, mt0), mn1 = fmaxf(m1, mt1);
            const float a0 = __expf(m0 - mn0), a1 = __expf(m1 - mn1);
            m0 = mn0; m1 = mn1;
            float sum0 = 0.f, sum1 = 0.f;
            #pragma unroll
            for (int nt = 0; nt < 4; nt++) {
                s[nt][0] = __expf(s[nt][0] - mn0);
                s[nt][1] = __expf(s[nt][1] - mn0);
                s[nt][2] = __expf(s[nt][2] - mn1);
                s[nt][3] = __expf(s[nt][3] - mn1);
                sum0 += s[nt][0] + s[nt][1];
                sum1 += s[nt][2] + s[nt][3];
            }
            sum0 += __shfl_xor_sync(0xffffffffu, sum0, 1);
            sum0 += __shfl_xor_sync(0xffffffffu, sum0, 2);
            sum1 += __shfl_xor_sync(0xffffffffu, sum1, 1);
            sum1 += __shfl_xor_sync(0xffffffffu, sum1, 2);
            l0 = l0 * a0 + sum0;
            l1 = l1 * a1 + sum1;
            #pragma unroll
            for (int nt = 0; nt < 8; nt++) {
                o[nt][0] *= a0; o[nt][1] *= a0;
                o[nt][2] *= a1; o[nt][3] *= a1;
            }
            {
                const int pr0 = (16 * w + lg) * VST;
                const int pr1 = (16 * w + 8 + lg) * VST;
                #pragma unroll
                for (int nt = 0; nt < 4; nt++) {
                    float2 p01 = make_float2(tf32_rna(s[nt][0]), tf32_rna(s[nt][1]));
                    float2 p23 = make_float2(tf32_rna(s[nt][2]), tf32_rna(s[nt][3]));
                    *(float2*)(s_ps + pr0 + nt * 8 + 2 * lt) = p01;
                    *(float2*)(s_ps + pr1 + nt * 8 + 2 * lt) = p23;
                }
            }
            __syncwarp();
            unsigned pa[4][4];
            #pragma unroll
            for (int kc = 0; kc < 4; kc++) {
                pa[kc][0] = fu(s_ps[(16 * w + lg) * VST + kc * 8 + lt]);
                pa[kc][1] = fu(s_ps[(16 * w + 8 + lg) * VST + kc * 8 + lt]);
                pa[kc][2] = fu(s_ps[(16 * w + lg) * VST + kc * 8 + 4 + lt]);
                pa[kc][3] = fu(s_ps[(16 * w + 8 + lg) * VST + kc * 8 + 4 + lt]);
            }
            #pragma unroll
            for (int nt = 0; nt < 8; nt++) {
                const int vr = (nt * 8 + lg) * VST;
                #pragma unroll
                for (int kc = 0; kc < 4; kc++) {
                    unsigned vb[2];
                    vb[0] = fu(s_vt[vr + kc * 8 + lt]);
                    vb[1] = fu(s_vt[vr + kc * 8 + 4 + lt]);
                    mma_tf32(o[nt], pa[kc], vb);
                }
            }
        }
    }

    const float inv0 = 1.0f / l0, inv1 = 1.0f / l1;
    const int b = bh >> 4, h = bh & 15;
    float* dst0 = g_attn + ((size_t)b * SEQ + rg0) * DMODEL + h * DK;
    float* dst1 = g_attn + ((size_t)b * SEQ + rg1) * DMODEL + h * DK;
    #pragma unroll
    for (int nt = 0; nt < 8; nt++) {
        *(float2*)(dst0 + nt * 8 + 2 * lt) = make_float2(o[nt][0] * inv0, o[nt][1] * inv0);
        *(float2*)(dst1 + nt * 8 + 2 * lt) = make_float2(o[nt][2] * inv1, o[nt][3] * inv1);
    }
}

// ============================================================
extern "C" void kernel_launch(void* const* d_in, const int* in_sizes, int n_in,
                              void* d_out, int out_size)
{
    const float* x  = (const float*)d_in[0];
    const float* WQ = (const float*)d_in[1];
    const float* WK = (const float*)d_in[2];
    const float* WV = (const float*)d_in[3];
    const float* WO = (const float*)d_in[4];
    const int*   tp = (const int*)d_in[5];
    float* out = (float*)d_out;

    rope_table_kernel<<<SEQ, DK>>>(tp);
    qkv_mma_kernel<<<dim3(3 * DMODEL / 64, BATCH * SEQ / 128), 256>>>(x, WQ, WK, WV);
    attn_mma_kernel<<<dim3(SEQ / 64, NBH), 128>>>();
    out_mma_kernel<<<dim3(DMODEL / 64, BATCH * SEQ / 128), 256>>>(WO, out);
}

// round 11
// speedup vs baseline: 2.0355x; 1.1155x over previous
#include <cuda_runtime.h>
#include <math.h>

// Problem constants
#define BATCH 2
#define SEQ   2048
#define DMODEL 1024
#define NHEAD 16
#define DK    64
#define NBH   (BATCH*NHEAD)

// -------- scratch (no cudaMalloc allowed) --------
__device__ float g_Q[NBH * SEQ * DK];      // [b,h,s,d]
__device__ float g_K[NBH * SEQ * DK];
__device__ float g_V[NBH * SEQ * DK];
__device__ float g_attn[BATCH * SEQ * DMODEL]; // [b,s, h*dk]
__device__ float g_cos[SEQ * DK];
__device__ float g_sin[SEQ * DK];

// ============================================================
// Kernel 0: RoPE tables
// ============================================================
__global__ void rope_table_kernel(const int* __restrict__ tp) {
    int s = blockIdx.x;
    int d = threadIdx.x;
    int k = d >> 1;
    double freq = exp(-(double)(2 * k) / 64.0 * log(10000.0));
    double ang = (double)tp[s] * freq;
    g_cos[s * DK + d] = (float)cos(ang);
    g_sin[s * DK + d] = (float)sin(ang);
}

// ============================================================
// tf32 helpers
// ============================================================
__device__ __forceinline__ float tf32_rna(float x) {
    unsigned u;
    asm("cvt.rna.tf32.f32 %0, %1;" : "=r"(u) : "f"(x));
    return __uint_as_float(u);
}
__device__ __forceinline__ void split4(float4 v, float4& h, float4& l) {
    h.x = tf32_rna(v.x); l.x = tf32_rna(v.x - h.x);
    h.y = tf32_rna(v.y); l.y = tf32_rna(v.y - h.y);
    h.z = tf32_rna(v.z); l.z = tf32_rna(v.z - h.z);
    h.w = tf32_rna(v.w); l.w = tf32_rna(v.w - h.w);
}
// Truncation split: hi = tf32-prefix of x (LOP), lo = x - hi (exact FADD).
// Both passed raw to the MMA: hi is already tf32-exact; lo's HW truncation
// only perturbs the correction term (~2^-21 relative). No cvt in hot path.
__device__ __forceinline__ void splitu(float x, unsigned& h, unsigned& l) {
    unsigned u = __float_as_uint(x) & 0xffffe000u;
    h = u;
    l = __float_as_uint(x - __uint_as_float(u));
}
__device__ __forceinline__ void mma_tf32(float c[4], const unsigned a[4], const unsigned b[2]) {
    asm volatile(
        "mma.sync.aligned.m16n8k8.row.col.f32.tf32.tf32.f32 "
        "{%0,%1,%2,%3}, {%4,%5,%6,%7}, {%8,%9}, {%0,%1,%2,%3};"
        : "+f"(c[0]), "+f"(c[1]), "+f"(c[2]), "+f"(c[3])
        : "r"(a[0]), "r"(a[1]), "r"(a[2]), "r"(a[3]), "r"(b[0]), "r"(b[1]));
}
__device__ __forceinline__ unsigned fu(float x) { return __float_as_uint(x); }

__device__ __forceinline__ void cp16(float* smem, const float* gmem) {
    unsigned saddr = (unsigned)__cvta_generic_to_shared(smem);
    asm volatile("cp.async.ca.shared.global [%0], [%1], 16;" :: "r"(saddr), "l"(gmem) : "memory");
}

// ---- GEMM smem layout: raw fp32, TRIPLE-buffered (3 x 15.4KB = 46KB) ----
#define GS 20
#define SMA 0
#define SMB (128*GS)
#define BUFSZ (192*GS)          // 3840 floats per stage
#define NSTAGE 3
#define SM_TOT (NSTAGE*BUFSZ)   // 11520 floats = 46080 B

// ============================================================
// Pipelined GEMM mainloop: C[m,n] = sum_k A[m,k]*B[n,k]
// ============================================================
__device__ __forceinline__ void gemm_issue_copy(
    const float* __restrict__ Ap, const float* __restrict__ Bp,
    int kb, float* buf, int tid)
{
    const int r0 = tid >> 2;          // 0..63
    const int q0 = (tid & 3) * 4;     // 0,4,8,12
    cp16(buf + SMA + r0 * GS + q0, Ap + (size_t)r0 * DMODEL + kb + q0);
    cp16(buf + SMA + (r0 + 64) * GS + q0, Ap + (size_t)(r0 + 64) * DMODEL + kb + q0);
    cp16(buf + SMB + r0 * GS + q0, Bp + (size_t)r0 * DMODEL + kb + q0);
    asm volatile("cp.async.commit_group;" ::: "memory");
}

__device__ __forceinline__ void gemm_compute(
    const float* buf, float c[2][4][4], int wm, int wn, int lg, int lt)
{
    #pragma unroll
    for (int k0 = 0; k0 < 16; k0 += 8) {
        unsigned ah[2][4], al[2][4], bh[4][2], bl[4][2];
        #pragma unroll
        for (int mt = 0; mt < 2; mt++) {
            const int r = wm + mt * 16 + lg;
            splitu(buf[SMA + r * GS + k0 + lt],           ah[mt][0], al[mt][0]);
            splitu(buf[SMA + (r + 8) * GS + k0 + lt],     ah[mt][1], al[mt][1]);
            splitu(buf[SMA + r * GS + k0 + 4 + lt],       ah[mt][2], al[mt][2]);
            splitu(buf[SMA + (r + 8) * GS + k0 + 4 + lt], ah[mt][3], al[mt][3]);
        }
        #pragma unroll
        for (int nt = 0; nt < 4; nt++) {
            const int cc = wn + nt * 8 + lg;
            splitu(buf[SMB + cc * GS + k0 + lt],     bh[nt][0], bl[nt][0]);
            splitu(buf[SMB + cc * GS + k0 + 4 + lt], bh[nt][1], bl[nt][1]);
        }
        #pragma unroll
        for (int mt = 0; mt < 2; mt++)
            #pragma unroll
            for (int nt = 0; nt < 4; nt++) {
                mma_tf32(c[mt][nt], ah[mt], bh[nt]);
                mma_tf32(c[mt][nt], ah[mt], bl[nt]);
                mma_tf32(c[mt][nt], al[mt], bh[nt]);
            }
    }
}

__device__ __forceinline__ void mma_mainloop(
    const float* __restrict__ Ap, const float* __restrict__ Bp,
    float* sm, float c[2][4][4])
{
    const int tid = threadIdx.x;
    const int lane = tid & 31;
    const int wid = tid >> 5;
    const int wm = (wid & 3) * 32;
    const int wn = (wid >> 2) * 32;
    const int lg = lane >> 2;
    const int lt = lane & 3;
    const int NB = DMODEL / 16;   // 64

    gemm_issue_copy(Ap, Bp, 0, sm, tid);
    gemm_issue_copy(Ap, Bp, 16, sm + BUFSZ, tid);

    for (int i = 0; i < NB; i++) {
        // group ledger before wait: pending = {i, i+1} (or {i} on last iter)
        if (i + 1 < NB)
            asm volatile("cp.async.wait_group 1;" ::: "memory");
        else
            asm volatile("cp.async.wait_group 0;" ::: "memory");
        __syncthreads();   // also guarantees buf[(i+2)%3] (= buf[(i-1)%3]) fully consumed
        if (i + 2 < NB)
            gemm_issue_copy(Ap, Bp, (i + 2) * 16, sm + ((i + 2) % NSTAGE) * BUFSZ, tid);
        gemm_compute(sm + (i % NSTAGE) * BUFSZ, c, wm, wn, lg, lt);
    }
}

// ============================================================
// Kernel 1: QKV projection via 3xTF32 MMA (+RoPE epilogue)
// ============================================================
__global__ __launch_bounds__(256, 3) void qkv_mma_kernel(
    const float* __restrict__ x,
    const float* __restrict__ WQ,
    const float* __restrict__ WK,
    const float* __restrict__ WV)
{
    __shared__ float sm[SM_TOT];
    const int m0 = blockIdx.y * 128;
    const int e0 = blockIdx.x * 64;
    const int sect = e0 >> 10;
    const float* Wp = (sect == 0 ? WQ : (sect == 1 ? WK : WV)) + (size_t)(e0 & 1023) * DMODEL;
    const float* Ap = x + (size_t)m0 * DMODEL;

    float c[2][4][4] = {};
    mma_mainloop(Ap, Wp, sm, c);

    const int lane = threadIdx.x & 31;
    const int wid = threadIdx.x >> 5;
    const int wm = (wid & 3) * 32;
    const int wn = (wid >> 2) * 32;
    const int lg = lane >> 2, lt = lane & 3;
    float* dst = (sect == 0) ? g_Q : ((sect == 1) ? g_K : g_V);

    #pragma unroll
    for (int mt = 0; mt < 2; mt++) {
        #pragma unroll
        for (int nt = 0; nt < 4; nt++) {
            const int col = e0 + wn + nt * 8 + 2 * lt;
            const int ec = col & 1023;
            const int h = ec >> 6;
            const int d = ec & 63;
            #pragma unroll
            for (int half = 0; half < 2; half++) {
                const int row = m0 + wm + mt * 16 + lg + half * 8;
                const float v0 = c[mt][nt][half * 2 + 0];
                const float v1 = c[mt][nt][half * 2 + 1];
                const int b = row >> 11;
                const int srow = row & (SEQ - 1);
                const size_t oidx = (((size_t)(b * NHEAD + h)) * SEQ + srow) * DK + d;
                float2 o;
                if (sect < 2) {
                    const float cs = g_cos[srow * DK + d];
                    const float sn = g_sin[srow * DK + d];
                    o.x = v0 * cs - v1 * sn;
                    o.y = v1 * cs + v0 * sn;
                } else {
                    o.x = v0; o.y = v1;
                }
                *(float2*)(dst + oidx) = o;
            }
        }
    }
}

// ============================================================
// Kernel 3: output projection via 3xTF32 MMA
// ============================================================
__global__ __launch_bounds__(256, 3) void out_mma_kernel(
    const float* __restrict__ WO, float* __restrict__ out)
{
    __shared__ float sm[SM_TOT];
    const int m0 = blockIdx.y * 128;
    const int e0 = blockIdx.x * 64;
    const float* Ap = g_attn + (size_t)m0 * DMODEL;
    const float* Wp = WO + (size_t)e0 * DMODEL;

    float c[2][4][4] = {};
    mma_mainloop(Ap, Wp, sm, c);

    const int lane = threadIdx.x & 31;
    const int wid = threadIdx.x >> 5;
    const int wm = (wid & 3) * 32;
    const int wn = (wid >> 2) * 32;
    const int lg = lane >> 2, lt = lane & 3;

    #pragma unroll
    for (int mt = 0; mt < 2; mt++) {
        #pragma unroll
        for (int nt = 0; nt < 4; nt++) {
            const int col = e0 + wn + nt * 8 + 2 * lt;
            #pragma unroll
            for (int half = 0; half < 2; half++) {
                const int row = m0 + wm + mt * 16 + lg + half * 8;
                float2 o;
                o.x = c[mt][nt][half * 2 + 0];
                o.y = c[mt][nt][half * 2 + 1];
                *(float2*)(out + (size_t)row * DMODEL + col) = o;
            }
        }
    }
}

// ============================================================
// Kernel 2: causal flash attention via tensor-core MMA (unchanged).
// ============================================================
#define KST 68
#define VST 36

__global__ __launch_bounds__(128) void attn_mma_kernel()
{
    __shared__ float s_k[64 * KST];
    __shared__ float s_vt[64 * VST];
    __shared__ float s_ps[64 * VST];

    const int qt = gridDim.x - 1 - blockIdx.x;
    const int bh = blockIdx.y;
    const int tid = threadIdx.x;
    const int w = tid >> 5;
    const int lane = tid & 31;
    const int lg = lane >> 2, lt = lane & 3;
    const int q0 = qt * 64;

    const float* Qb = g_Q + (size_t)bh * SEQ * DK;
    const float* Kb = g_K + (size_t)bh * SEQ * DK;
    const float* Vb = g_V + (size_t)bh * SEQ * DK;

    {
        const int row = tid & 63, half = tid >> 6;
        const float* src = Qb + (size_t)(q0 + row) * DK + 32 * half;
        float* dq = s_k + row * KST + 32 * half;
        #pragma unroll
        for (int i = 0; i < 8; i++) {
            float4 v = *(const float4*)(src + 4 * i);
            v.x *= 0.125f; v.y *= 0.125f; v.z *= 0.125f; v.w *= 0.125f;
            *(float4*)(dq + 4 * i) = v;
        }
    }
    __syncthreads();

    unsigned qh[8][4], ql[8][4];
    {
        const int r0 = 16 * w + lg;
        #pragma unroll
        for (int kc = 0; kc < 8; kc++) {
            float f[4];
            f[0] = s_k[r0 * KST + kc * 8 + lt];
            f[1] = s_k[(r0 + 8) * KST + kc * 8 + lt];
            f[2] = s_k[r0 * KST + kc * 8 + 4 + lt];
            f[3] = s_k[(r0 + 8) * KST + kc * 8 + 4 + lt];
            #pragma unroll
            for (int i = 0; i < 4; i++) {
                float hi = tf32_rna(f[i]);
                qh[kc][i] = fu(hi);
                ql[kc][i] = fu(tf32_rna(f[i] - hi));
            }
        }
    }

    float o[8][4];
    #pragma unroll
    for (int nt = 0; nt < 8; nt++)
        #pragma unroll
        for (int i = 0; i < 4; i++) o[nt][i] = 0.f;
    float m0 = -1e30f, m1 = -1e30f, l0 = 0.f, l1 = 0.f;
    const int rg0 = q0 + 16 * w + lg;
    const int rg1 = rg0 + 8;
    const int nsub = 2 * qt + 2;

    for (int s32 = 0; s32 < nsub; s32++) {
        const int k32 = s32 * 32;
        __syncthreads();

        {
            const int key = tid & 31, part = tid >> 5;
            const float* ksrc = Kb + (size_t)(k32 + key) * DK + 16 * part;
            #pragma unroll
            for (int i = 0; i < 4; i++) {
                float4 v = *(const float4*)(ksrc + 4 * i);
                float4 h, l; split4(v, h, l);
                *(float4*)(s_k + key * KST + 16 * part + 4 * i) = h;
                *(float4*)(s_k + 32 * KST + key * KST + 16 * part + 4 * i) = l;
            }
            const float* vsrc = Vb + (size_t)(k32 + key) * DK + 16 * part;
            #pragma unroll
            for (int i = 0; i < 4; i++) {
                float4 v = *(const float4*)(vsrc + 4 * i);
                s_vt[(16 * part + 4 * i + 0) * VST + key] = tf32_rna(v.x);
                s_vt[(16 * part + 4 * i + 1) * VST + key] = tf32_rna(v.y);
                s_vt[(16 * part + 4 * i + 2) * VST + key] = tf32_rna(v.z);
                s_vt[(16 * part + 4 * i + 3) * VST + key] = tf32_rna(v.w);
            }
        }
        __syncthreads();

        const bool active = (k32 <= q0 + 16 * w + 15);
        if (active) {
            float s[4][4];
            #pragma unroll
            for (int nt = 0; nt < 4; nt++)
                #pragma unroll
                for (int i = 0; i < 4; i++) s[nt][i] = 0.f;
            #pragma unroll
            for (int nt = 0; nt < 4; nt++) {
                const int kr = (nt * 8 + lg) * KST;
                #pragma unroll
                for (int kc = 0; kc < 8; kc++) {
                    unsigned bhf[2], blf[2];
                    bhf[0] = fu(s_k[kr + kc * 8 + lt]);
                    bhf[1] = fu(s_k[kr + kc * 8 + 4 + lt]);
                    blf[0] = fu(s_k[32 * KST + kr + kc * 8 + lt]);
                    blf[1] = fu(s_k[32 * KST + kr + kc * 8 + 4 + lt]);
                    mma_tf32(s[nt], qh[kc], bhf);
                    mma_tf32(s[nt], ql[kc], bhf);
                    mma_tf32(s[nt], qh[kc], blf);
                }
            }
            if (k32 + 31 > rg0) {
                #pragma unroll
                for (int nt = 0; nt < 4; nt++) {
                    const int j = k32 + nt * 8 + 2 * lt;
                    if (j > rg0)     s[nt][0] = -1e30f;
                    if (j + 1 > rg0) s[nt][1] = -1e30f;
                }
            }
            if (k32 + 31 > rg1) {
                #pragma unroll
                for (int nt = 0; nt < 4; nt++) {
                    const int j = k32 + nt * 8 + 2 * lt;
                    if (j > rg1)     s[nt][2] = -1e30f;
                    if (j + 1 > rg1) s[nt][3] = -1e30f;
                }
            }
            float mt0 = -1e30f, mt1 = -1e30f;
            #pragma unroll
            for (int nt = 0; nt < 4; nt++) {
                mt0 = fmaxf(mt0, fmaxf(s[nt][0], s[nt][1]));
                mt1 = fmaxf(mt1, fmaxf(s[nt][2], s[nt][3]));
            }
            mt0 = fmaxf(mt0, __shfl_xor_sync(0xffffffffu, mt0, 1));
            mt0 = fmaxf(mt0, __shfl_xor_sync(0xffffffffu, mt0, 2));
            mt1 = fmaxf(mt1, __shfl_xor_sync(0xffffffffu, mt1, 1));
            mt1 = fmaxf(mt1, __shfl_xor_sync(0xffffffffu, mt1, 2));
            const float mn0 = fmaxf(m0, mt0), mn1 = fmaxf(m1, mt1);
            const float a0 = __expf(m0 - mn0), a1 = __expf(m1 - mn1);
            m0 = mn0; m1 = mn1;
            float sum0 = 0.f, sum1 = 0.f;
            #pragma unroll
            for (int nt = 0; nt < 4; nt++) {
                s[nt][0] = __expf(s[nt][0] - mn0);
                s[nt][1] = __expf(s[nt][1] - mn0);
                s[nt][2] = __expf(s[nt][2] - mn1);
                s[nt][3] = __expf(s[nt][3] - mn1);
                sum0 += s[nt][0] + s[nt][1];
                sum1 += s[nt][2] + s[nt][3];
            }
            sum0 += __shfl_xor_sync(0xffffffffu, sum0, 1);
            sum0 += __shfl_xor_sync(0xffffffffu, sum0, 2);
            sum1 += __shfl_xor_sync(0xffffffffu, sum1, 1);
            sum1 += __shfl_xor_sync(0xffffffffu, sum1, 2);
            l0 = l0 * a0 + sum0;
            l1 = l1 * a1 + sum1;
            #pragma unroll
            for (int nt = 0; nt < 8; nt++) {
                o[nt][0] *= a0; o[nt][1] *= a0;
                o[nt][2] *= a1; o[nt][3] *= a1;
            }
            {
                const int pr0 = (16 * w + lg) * VST;
                const int pr1 = (16 * w + 8 + lg) * VST;
                #pragma unroll
                for (int nt = 0; nt < 4; nt++) {
                    float2 p01 = make_float2(tf32_rna(s[nt][0]), tf32_rna(s[nt][1]));
                    float2 p23 = make_float2(tf32_rna(s[nt][2]), tf32_rna(s[nt][3]));
                    *(float2*)(s_ps + pr0 + nt * 8 + 2 * lt) = p01;
                    *(float2*)(s_ps + pr1 + nt * 8 + 2 * lt) = p23;
                }
            }
            __syncwarp();
            unsigned pa[4][4];
            #pragma unroll
            for (int kc = 0; kc < 4; kc++) {
                pa[kc][0] = fu(s_ps[(16 * w + lg) * VST + kc * 8 + lt]);
                pa[kc][1] = fu(s_ps[(16 * w + 8 + lg) * VST + kc * 8 + lt]);
                pa[kc][2] = fu(s_ps[(16 * w + lg) * VST + kc * 8 + 4 + lt]);
                pa[kc][3] = fu(s_ps[(16 * w + 8 + lg) * VST + kc * 8 + 4 + lt]);
            }
            #pragma unroll
            for (int nt = 0; nt < 8; nt++) {
                const int vr = (nt * 8 + lg) * VST;
                #pragma unroll
                for (int kc = 0; kc < 4; kc++) {
                    unsigned vb[2];
                    vb[0] = fu(s_vt[vr + kc * 8 + lt]);
                    vb[1] = fu(s_vt[vr + kc * 8 + 4 + lt]);
                    mma_tf32(o[nt], pa[kc], vb);
                }
            }
        }
    }

    const float inv0 = 1.0f / l0, inv1 = 1.0f / l1;
    const int b = bh >> 4, h = bh & 15;
    float* dst0 = g_attn + ((size_t)b * SEQ + rg0) * DMODEL + h * DK;
    float* dst1 = g_attn + ((size_t)b * SEQ + rg1) * DMODEL + h * DK;
    #pragma unroll
    for (int nt = 0; nt < 8; nt++) {
        *(float2*)(dst0 + nt * 8 + 2 * lt) = make_float2(o[nt][0] * inv0, o[nt][1] * inv0);
        *(float2*)(dst1 + nt * 8 + 2 * lt) = make_float2(o[nt][2] * inv1, o[nt][3] * inv1);
    }
}

// ============================================================
extern "C" void kernel_launch(void* const* d_in, const int* in_sizes, int n_in,
                              void* d_out, int out_size)
{
    const float* x  = (const float*)d_in[0];
    const float* WQ = (const float*)d_in[1];
    const float* WK = (const float*)d_in[2];
    const float* WV = (const float*)d_in[3];
    const float* WO = (const float*)d_in[4];
    const int*   tp = (const int*)d_in[5];
    float* out = (float*)d_out;

    rope_table_kernel<<<SEQ, DK>>>(tp);
    qkv_mma_kernel<<<dim3(3 * DMODEL / 64, BATCH * SEQ / 128), 256>>>(x, WQ, WK, WV);
    attn_mma_kernel<<<dim3(SEQ / 64, NBH), 128>>>();
    out_mma_kernel<<<dim3(DMODEL / 64, BATCH * SEQ / 128), 256>>>(WO, out);
}

// round 12
// speedup vs baseline: 2.4166x; 1.1872x over previous
#include <cuda_runtime.h>
#include <math.h>

// Problem constants
#define BATCH 2
#define SEQ   2048
#define DMODEL 1024
#define NHEAD 16
#define DK    64
#define NBH   (BATCH*NHEAD)

// -------- scratch (no cudaMalloc allowed) --------
__device__ float g_Q[NBH * SEQ * DK];      // [b,h,s,d]
__device__ float g_K[NBH * SEQ * DK];
__device__ float g_V[NBH * SEQ * DK];
__device__ float g_attn[BATCH * SEQ * DMODEL]; // [b,s, h*dk]
__device__ float g_cos[SEQ * DK];
__device__ float g_sin[SEQ * DK];

// ============================================================
// Kernel 0: RoPE tables
// ============================================================
__global__ void rope_table_kernel(const int* __restrict__ tp) {
    int s = blockIdx.x;
    int d = threadIdx.x;
    int k = d >> 1;
    double freq = exp(-(double)(2 * k) / 64.0 * log(10000.0));
    double ang = (double)tp[s] * freq;
    g_cos[s * DK + d] = (float)cos(ang);
    g_sin[s * DK + d] = (float)sin(ang);
}

// ============================================================
// tf32 helpers
// ============================================================
__device__ __forceinline__ float tf32_rna(float x) {
    unsigned u;
    asm("cvt.rna.tf32.f32 %0, %1;" : "=r"(u) : "f"(x));
    return __uint_as_float(u);
}
// Truncation split: hi = tf32-prefix of x (LOP), lo = x - hi (exact FADD).
__device__ __forceinline__ void splitu(float x, unsigned& h, unsigned& l) {
    unsigned u = __float_as_uint(x) & 0xffffe000u;
    h = u;
    l = __float_as_uint(x - __uint_as_float(u));
}
__device__ __forceinline__ void mma_tf32(float c[4], const unsigned a[4], const unsigned b[2]) {
    asm volatile(
        "mma.sync.aligned.m16n8k8.row.col.f32.tf32.tf32.f32 "
        "{%0,%1,%2,%3}, {%4,%5,%6,%7}, {%8,%9}, {%0,%1,%2,%3};"
        : "+f"(c[0]), "+f"(c[1]), "+f"(c[2]), "+f"(c[3])
        : "r"(a[0]), "r"(a[1]), "r"(a[2]), "r"(a[3]), "r"(b[0]), "r"(b[1]));
}
__device__ __forceinline__ unsigned fu(float x) { return __float_as_uint(x); }

__device__ __forceinline__ void cp16(float* smem, const float* gmem) {
    unsigned saddr = (unsigned)__cvta_generic_to_shared(smem);
    asm volatile("cp.async.ca.shared.global [%0], [%1], 16;" :: "r"(saddr), "l"(gmem) : "memory");
}

// ---- GEMM smem layout: raw fp32, TRIPLE-buffered (validated round 11) ----
#define GS 20
#define SMA 0
#define SMB (128*GS)
#define BUFSZ (192*GS)
#define NSTAGE 3
#define SM_TOT (NSTAGE*BUFSZ)   // 46080 B

// ============================================================
// Pipelined GEMM mainloop (unchanged from passing round-11 kernel)
// ============================================================
__device__ __forceinline__ void gemm_issue_copy(
    const float* __restrict__ Ap, const float* __restrict__ Bp,
    int kb, float* buf, int tid)
{
    const int r0 = tid >> 2;
    const int q0 = (tid & 3) * 4;
    cp16(buf + SMA + r0 * GS + q0, Ap + (size_t)r0 * DMODEL + kb + q0);
    cp16(buf + SMA + (r0 + 64) * GS + q0, Ap + (size_t)(r0 + 64) * DMODEL + kb + q0);
    cp16(buf + SMB + r0 * GS + q0, Bp + (size_t)r0 * DMODEL + kb + q0);
    asm volatile("cp.async.commit_group;" ::: "memory");
}

__device__ __forceinline__ void gemm_compute(
    const float* buf, float c[2][4][4], int wm, int wn, int lg, int lt)
{
    #pragma unroll
    for (int k0 = 0; k0 < 16; k0 += 8) {
        unsigned ah[2][4], al[2][4], bh[4][2], bl[4][2];
        #pragma unroll
        for (int mt = 0; mt < 2; mt++) {
            const int r = wm + mt * 16 + lg;
            splitu(buf[SMA + r * GS + k0 + lt],           ah[mt][0], al[mt][0]);
            splitu(buf[SMA + (r + 8) * GS + k0 + lt],     ah[mt][1], al[mt][1]);
            splitu(buf[SMA + r * GS + k0 + 4 + lt],       ah[mt][2], al[mt][2]);
            splitu(buf[SMA + (r + 8) * GS + k0 + 4 + lt], ah[mt][3], al[mt][3]);
        }
        #pragma unroll
        for (int nt = 0; nt < 4; nt++) {
            const int cc = wn + nt * 8 + lg;
            splitu(buf[SMB + cc * GS + k0 + lt],     bh[nt][0], bl[nt][0]);
            splitu(buf[SMB + cc * GS + k0 + 4 + lt], bh[nt][1], bl[nt][1]);
        }
        #pragma unroll
        for (int mt = 0; mt < 2; mt++)
            #pragma unroll
            for (int nt = 0; nt < 4; nt++) {
                mma_tf32(c[mt][nt], ah[mt], bh[nt]);
                mma_tf32(c[mt][nt], ah[mt], bl[nt]);
                mma_tf32(c[mt][nt], al[mt], bh[nt]);
            }
    }
}

__device__ __forceinline__ void mma_mainloop(
    const float* __restrict__ Ap, const float* __restrict__ Bp,
    float* sm, float c[2][4][4])
{
    const int tid = threadIdx.x;
    const int lane = tid & 31;
    const int wid = tid >> 5;
    const int wm = (wid & 3) * 32;
    const int wn = (wid >> 2) * 32;
    const int lg = lane >> 2;
    const int lt = lane & 3;
    const int NB = DMODEL / 16;

    gemm_issue_copy(Ap, Bp, 0, sm, tid);
    gemm_issue_copy(Ap, Bp, 16, sm + BUFSZ, tid);

    for (int i = 0; i < NB; i++) {
        if (i + 1 < NB)
            asm volatile("cp.async.wait_group 1;" ::: "memory");
        else
            asm volatile("cp.async.wait_group 0;" ::: "memory");
        __syncthreads();
        if (i + 2 < NB)
            gemm_issue_copy(Ap, Bp, (i + 2) * 16, sm + ((i + 2) % NSTAGE) * BUFSZ, tid);
        gemm_compute(sm + (i % NSTAGE) * BUFSZ, c, wm, wn, lg, lt);
    }
}

// ============================================================
// Kernel 1: QKV projection via 3xTF32 MMA (+RoPE epilogue)
// ============================================================
__global__ __launch_bounds__(256, 3) void qkv_mma_kernel(
    const float* __restrict__ x,
    const float* __restrict__ WQ,
    const float* __restrict__ WK,
    const float* __restrict__ WV)
{
    __shared__ float sm[SM_TOT];
    const int m0 = blockIdx.y * 128;
    const int e0 = blockIdx.x * 64;
    const int sect = e0 >> 10;
    const float* Wp = (sect == 0 ? WQ : (sect == 1 ? WK : WV)) + (size_t)(e0 & 1023) * DMODEL;
    const float* Ap = x + (size_t)m0 * DMODEL;

    float c[2][4][4] = {};
    mma_mainloop(Ap, Wp, sm, c);

    const int lane = threadIdx.x & 31;
    const int wid = threadIdx.x >> 5;
    const int wm = (wid & 3) * 32;
    const int wn = (wid >> 2) * 32;
    const int lg = lane >> 2, lt = lane & 3;
    float* dst = (sect == 0) ? g_Q : ((sect == 1) ? g_K : g_V);

    #pragma unroll
    for (int mt = 0; mt < 2; mt++) {
        #pragma unroll
        for (int nt = 0; nt < 4; nt++) {
            const int col = e0 + wn + nt * 8 + 2 * lt;
            const int ec = col & 1023;
            const int h = ec >> 6;
            const int d = ec & 63;
            #pragma unroll
            for (int half = 0; half < 2; half++) {
                const int row = m0 + wm + mt * 16 + lg + half * 8;
                const float v0 = c[mt][nt][half * 2 + 0];
                const float v1 = c[mt][nt][half * 2 + 1];
                const int b = row >> 11;
                const int srow = row & (SEQ - 1);
                const size_t oidx = (((size_t)(b * NHEAD + h)) * SEQ + srow) * DK + d;
                float2 o;
                if (sect < 2) {
                    const float cs = g_cos[srow * DK + d];
                    const float sn = g_sin[srow * DK + d];
                    o.x = v0 * cs - v1 * sn;
                    o.y = v1 * cs + v0 * sn;
                } else {
                    o.x = v0; o.y = v1;
                }
                *(float2*)(dst + oidx) = o;
            }
        }
    }
}

// ============================================================
// Kernel 3: output projection via 3xTF32 MMA
// ============================================================
__global__ __launch_bounds__(256, 3) void out_mma_kernel(
    const float* __restrict__ WO, float* __restrict__ out)
{
    __shared__ float sm[SM_TOT];
    const int m0 = blockIdx.y * 128;
    const int e0 = blockIdx.x * 64;
    const float* Ap = g_attn + (size_t)m0 * DMODEL;
    const float* Wp = WO + (size_t)e0 * DMODEL;

    float c[2][4][4] = {};
    mma_mainloop(Ap, Wp, sm, c);

    const int lane = threadIdx.x & 31;
    const int wid = threadIdx.x >> 5;
    const int wm = (wid & 3) * 32;
    const int wn = (wid >> 2) * 32;
    const int lg = lane >> 2, lt = lane & 3;

    #pragma unroll
    for (int mt = 0; mt < 2; mt++) {
        #pragma unroll
        for (int nt = 0; nt < 4; nt++) {
            const int col = e0 + wn + nt * 8 + 2 * lt;
            #pragma unroll
            for (int half = 0; half < 2; half++) {
                const int row = m0 + wm + mt * 16 + lg + half * 8;
                float2 o;
                o.x = c[mt][nt][half * 2 + 0];
                o.y = c[mt][nt][half * 2 + 1];
                *(float2*)(out + (size_t)row * DMODEL + col) = o;
            }
        }
    }
}

// ============================================================
// Kernel 2: causal flash attention — cp.async-pipelined raw K/V,
// truncation splits (no cvt in hot path).
// K raw [key][d] @ stride 68 IS the S-phase B operand layout.
// V raw [key][d] @ stride 72 serves PV B-fragments directly
// (banks 8*lt+lg mod 32: conflict-free). No V transpose pass.
// ============================================================
#define KSTR 68
#define VSTR 72
#define PST  36
#define KVSTAGE (32*KSTR + 32*VSTR)   // 4480 floats per stage

__global__ __launch_bounds__(128) void attn_mma_kernel()
{
    __shared__ float smem[2 * KVSTAGE + 64 * PST];   // 45056 B
    float* s_ps = smem + 2 * KVSTAGE;

    const int qt = gridDim.x - 1 - blockIdx.x;   // LPT: heavy tiles first
    const int bh = blockIdx.y;
    const int tid = threadIdx.x;
    const int w = tid >> 5;
    const int lane = tid & 31;
    const int lg = lane >> 2, lt = lane & 3;
    const int q0 = qt * 64;

    const float* Qb = g_Q + (size_t)bh * SEQ * DK;
    const float* Kb = g_K + (size_t)bh * SEQ * DK;
    const float* Vb = g_V + (size_t)bh * SEQ * DK;

    // ---- stage Q (pre-scaled 1/8) through stage-0 buffer ----
    {
        const int row = tid & 63, half = tid >> 6;
        const float* src = Qb + (size_t)(q0 + row) * DK + 32 * half;
        float* dq = smem + row * KSTR + 32 * half;
        #pragma unroll
        for (int i = 0; i < 8; i++) {
            float4 v = *(const float4*)(src + 4 * i);
            v.x *= 0.125f; v.y *= 0.125f; v.z *= 0.125f; v.w *= 0.125f;
            *(float4*)(dq + 4 * i) = v;
        }
    }
    __syncthreads();

    // ---- extract Q A-fragments (hi/lo, truncation split) ----
    unsigned qh[8][4], ql[8][4];
    {
        const int r0 = 16 * w + lg;
        #pragma unroll
        for (int kc = 0; kc < 8; kc++) {
            float f[4];
            f[0] = smem[r0 * KSTR + kc * 8 + lt];
            f[1] = smem[(r0 + 8) * KSTR + kc * 8 + lt];
            f[2] = smem[r0 * KSTR + kc * 8 + 4 + lt];
            f[3] = smem[(r0 + 8) * KSTR + kc * 8 + 4 + lt];
            #pragma unroll
            for (int i = 0; i < 4; i++) splitu(f[i], qh[kc][i], ql[kc][i]);
        }
    }
    __syncthreads();   // all warps done with Q staging before cp.async overwrites

    float o[8][4];
    #pragma unroll
    for (int nt = 0; nt < 8; nt++)
        #pragma unroll
        for (int i = 0; i < 4; i++) o[nt][i] = 0.f;
    float m0 = -1e30f, m1 = -1e30f, l0 = 0.f, l1 = 0.f;
    const int rg0 = q0 + 16 * w + lg;
    const int rg1 = rg0 + 8;
    const int nsub = 2 * qt + 2;

    // issue subtile 0
    {
        #pragma unroll
        for (int j = 0; j < 4; j++) {
            const int f = tid + j * 128;          // float4 index 0..511
            const int row = f >> 4, c4 = (f & 15) * 4;
            cp16(smem + row * KSTR + c4, Kb + (size_t)row * DK + c4);
            cp16(smem + 32 * KSTR + row * VSTR + c4, Vb + (size_t)row * DK + c4);
        }
        asm volatile("cp.async.commit_group;" ::: "memory");
    }

    for (int s32 = 0; s32 < nsub; s32++) {
        // issue next subtile into the other stage
        if (s32 + 1 < nsub) {
            const int k32n = (s32 + 1) * 32;
            float* buf = smem + ((s32 + 1) & 1) * KVSTAGE;
            #pragma unroll
            for (int j = 0; j < 4; j++) {
                const int f = tid + j * 128;
                const int row = f >> 4, c4 = (f & 15) * 4;
                cp16(buf + row * KSTR + c4, Kb + (size_t)(k32n + row) * DK + c4);
                cp16(buf + 32 * KSTR + row * VSTR + c4, Vb + (size_t)(k32n + row) * DK + c4);
            }
            asm volatile("cp.async.commit_group;" ::: "memory");
            asm volatile("cp.async.wait_group 1;" ::: "memory");
        } else {
            asm volatile("cp.async.wait_group 0;" ::: "memory");
        }
        __syncthreads();

        const int k32 = s32 * 32;
        const float* kb = smem + (s32 & 1) * KVSTAGE;
        const float* vb = kb + 32 * KSTR;
        const bool active = (k32 <= q0 + 16 * w + 15);
        if (active) {
            // ---- S = Q*K^T (3xTF32, K split at fragment load) ----
            float s[4][4];
            #pragma unroll
            for (int nt = 0; nt < 4; nt++)
                #pragma unroll
                for (int i = 0; i < 4; i++) s[nt][i] = 0.f;
            #pragma unroll
            for (int nt = 0; nt < 4; nt++) {
                const int kr = (nt * 8 + lg) * KSTR;
                #pragma unroll
                for (int kc = 0; kc < 8; kc++) {
                    unsigned bhf[2], blf[2];
                    splitu(kb[kr + kc * 8 + lt],     bhf[0], blf[0]);
                    splitu(kb[kr + kc * 8 + 4 + lt], bhf[1], blf[1]);
                    mma_tf32(s[nt], qh[kc], bhf);
                    mma_tf32(s[nt], ql[kc], bhf);
                    mma_tf32(s[nt], qh[kc], blf);
                }
            }
            // ---- causal mask ----
            if (k32 + 31 > rg0) {
                #pragma unroll
                for (int nt = 0; nt < 4; nt++) {
                    const int j = k32 + nt * 8 + 2 * lt;
                    if (j > rg0)     s[nt][0] = -1e30f;
                    if (j + 1 > rg0) s[nt][1] = -1e30f;
                }
            }
            if (k32 + 31 > rg1) {
                #pragma unroll
                for (int nt = 0; nt < 4; nt++) {
                    const int j = k32 + nt * 8 + 2 * lt;
                    if (j > rg1)     s[nt][2] = -1e30f;
                    if (j + 1 > rg1) s[nt][3] = -1e30f;
                }
            }
            // ---- online softmax ----
            float mt0 = -1e30f, mt1 = -1e30f;
            #pragma unroll
            for (int nt = 0; nt < 4; nt++) {
                mt0 = fmaxf(mt0, fmaxf(s[nt][0], s[nt][1]));
                mt1 = fmaxf(mt1, fmaxf(s[nt][2], s[nt][3]));
            }
            mt0 = fmaxf(mt0, __shfl_xor_sync(0xffffffffu, mt0, 1));
            mt0 = fmaxf(mt0, __shfl_xor_sync(0xffffffffu, mt0, 2));
            mt1 = fmaxf(mt1, __shfl_xor_sync(0xffffffffu, mt1, 1));
            mt1 = fmaxf(mt1, __shfl_xor_sync(0xffffffffu, mt1, 2));
            const float mn0 = fmaxf(m0, mt0), mn1 = fmaxf(m1, mt1);
            const float a0 = __expf(m0 - mn0), a1 = __expf(m1 - mn1);
            m0 = mn0; m1 = mn1;
            float sum0 = 0.f, sum1 = 0.f;
            #pragma unroll
            for (int nt = 0; nt < 4; nt++) {
                s[nt][0] = __expf(s[nt][0] - mn0);
                s[nt][1] = __expf(s[nt][1] - mn0);
                s[nt][2] = __expf(s[nt][2] - mn1);
                s[nt][3] = __expf(s[nt][3] - mn1);
                sum0 += s[nt][0] + s[nt][1];
                sum1 += s[nt][2] + s[nt][3];
            }
            sum0 += __shfl_xor_sync(0xffffffffu, sum0, 1);
            sum0 += __shfl_xor_sync(0xffffffffu, sum0, 2);
            sum1 += __shfl_xor_sync(0xffffffffu, sum1, 1);
            sum1 += __shfl_xor_sync(0xffffffffu, sum1, 2);
            l0 = l0 * a0 + sum0;
            l1 = l1 * a1 + sum1;
            #pragma unroll
            for (int nt = 0; nt < 8; nt++) {
                o[nt][0] *= a0; o[nt][1] *= a0;
                o[nt][2] *= a1; o[nt][3] *= a1;
            }
            // ---- stage P (rna, hedged) to own warp's rows ----
            {
                const int pr0 = (16 * w + lg) * PST;
                const int pr1 = (16 * w + 8 + lg) * PST;
                #pragma unroll
                for (int nt = 0; nt < 4; nt++) {
                    float2 p01 = make_float2(tf32_rna(s[nt][0]), tf32_rna(s[nt][1]));
                    float2 p23 = make_float2(tf32_rna(s[nt][2]), tf32_rna(s[nt][3]));
                    *(float2*)(s_ps + pr0 + nt * 8 + 2 * lt) = p01;
                    *(float2*)(s_ps + pr1 + nt * 8 + 2 * lt) = p23;
                }
            }
            __syncwarp();
            // ---- PV: O += P * V (V raw, HW-truncated) ----
            unsigned pa[4][4];
            #pragma unroll
            for (int kc = 0; kc < 4; kc++) {
                pa[kc][0] = fu(s_ps[(16 * w + lg) * PST + kc * 8 + lt]);
                pa[kc][1] = fu(s_ps[(16 * w + 8 + lg) * PST + kc * 8 + lt]);
                pa[kc][2] = fu(s_ps[(16 * w + lg) * PST + kc * 8 + 4 + lt]);
                pa[kc][3] = fu(s_ps[(16 * w + 8 + lg) * PST + kc * 8 + 4 + lt]);
            }
            #pragma unroll
            for (int nt = 0; nt < 8; nt++) {
                #pragma unroll
                for (int kc = 0; kc < 4; kc++) {
                    unsigned vbf[2];
                    vbf[0] = fu(vb[(kc * 8 + lt) * VSTR + nt * 8 + lg]);
                    vbf[1] = fu(vb[(kc * 8 + 4 + lt) * VSTR + nt * 8 + lg]);
                    mma_tf32(o[nt], pa[kc], vbf);
                }
            }
        }
        __syncthreads();   // compute done before next iter's issue overwrites this stage
    }

    // ---- normalize + write ----
    const float inv0 = 1.0f / l0, inv1 = 1.0f / l1;
    const int b = bh >> 4, h = bh & 15;
    float* dst0 = g_attn + ((size_t)b * SEQ + rg0) * DMODEL + h * DK;
    float* dst1 = g_attn + ((size_t)b * SEQ + rg1) * DMODEL + h * DK;
    #pragma unroll
    for (int nt = 0; nt < 8; nt++) {
        *(float2*)(dst0 + nt * 8 + 2 * lt) = make_float2(o[nt][0] * inv0, o[nt][1] * inv0);
        *(float2*)(dst1 + nt * 8 + 2 * lt) = make_float2(o[nt][2] * inv1, o[nt][3] * inv1);
    }
}

// ============================================================
extern "C" void kernel_launch(void* const* d_in, const int* in_sizes, int n_in,
                              void* d_out, int out_size)
{
    const float* x  = (const float*)d_in[0];
    const float* WQ = (const float*)d_in[1];
    const float* WK = (const float*)d_in[2];
    const float* WV = (const float*)d_in[3];
    const float* WO = (const float*)d_in[4];
    const int*   tp = (const int*)d_in[5];
    float* out = (float*)d_out;

    rope_table_kernel<<<SEQ, DK>>>(tp);
    qkv_mma_kernel<<<dim3(3 * DMODEL / 64, BATCH * SEQ / 128), 256>>>(x, WQ, WK, WV);
    attn_mma_kernel<<<dim3(SEQ / 64, NBH), 128>>>();
    out_mma_kernel<<<dim3(DMODEL / 64, BATCH * SEQ / 128), 256>>>(WO, out);
}

// round 13
// speedup vs baseline: 2.4532x; 1.0152x over previous
#include <cuda_runtime.h>
#include <math.h>

// Problem constants
#define BATCH 2
#define SEQ   2048
#define DMODEL 1024
#define NHEAD 16
#define DK    64
#define NBH   (BATCH*NHEAD)

// -------- scratch (no cudaMalloc allowed) --------
__device__ float g_Q[NBH * SEQ * DK];      // [b,h,s,d]
__device__ float g_K[NBH * SEQ * DK];
__device__ float g_V[NBH * SEQ * DK];
__device__ float g_attn[BATCH * SEQ * DMODEL]; // [b,s, h*dk]
__device__ float g_cos[SEQ * DK];
__device__ float g_sin[SEQ * DK];

// ============================================================
// Kernel 0: RoPE tables
// ============================================================
__global__ void rope_table_kernel(const int* __restrict__ tp) {
    int s = blockIdx.x;
    int d = threadIdx.x;
    int k = d >> 1;
    double freq = exp(-(double)(2 * k) / 64.0 * log(10000.0));
    double ang = (double)tp[s] * freq;
    g_cos[s * DK + d] = (float)cos(ang);
    g_sin[s * DK + d] = (float)sin(ang);
}

// ============================================================
// tf32 helpers
// ============================================================
__device__ __forceinline__ float tf32_rna(float x) {
    unsigned u;
    asm("cvt.rna.tf32.f32 %0, %1;" : "=r"(u) : "f"(x));
    return __uint_as_float(u);
}
// Truncation split: hi = tf32-prefix of x (LOP), lo = x - hi (exact FADD).
__device__ __forceinline__ void splitu(float x, unsigned& h, unsigned& l) {
    unsigned u = __float_as_uint(x) & 0xffffe000u;
    h = u;
    l = __float_as_uint(x - __uint_as_float(u));
}
__device__ __forceinline__ void mma_tf32(float c[4], const unsigned a[4], const unsigned b[2]) {
    asm volatile(
        "mma.sync.aligned.m16n8k8.row.col.f32.tf32.tf32.f32 "
        "{%0,%1,%2,%3}, {%4,%5,%6,%7}, {%8,%9}, {%0,%1,%2,%3};"
        : "+f"(c[0]), "+f"(c[1]), "+f"(c[2]), "+f"(c[3])
        : "r"(a[0]), "r"(a[1]), "r"(a[2]), "r"(a[3]), "r"(b[0]), "r"(b[1]));
}
__device__ __forceinline__ unsigned fu(float x) { return __float_as_uint(x); }

__device__ __forceinline__ void cp16(float* smem, const float* gmem) {
    unsigned saddr = (unsigned)__cvta_generic_to_shared(smem);
    asm volatile("cp.async.ca.shared.global [%0], [%1], 16;" :: "r"(saddr), "l"(gmem) : "memory");
}

// ---- GEMM smem layout: raw fp32, TRIPLE-buffered (validated round 11) ----
#define GS 20
#define SMA 0
#define SMB (128*GS)
#define BUFSZ (192*GS)
#define NSTAGE 3
#define SM_TOT (NSTAGE*BUFSZ)   // 46080 B

// ============================================================
// Pipelined GEMM mainloop (unchanged from passing round-12 kernel)
// ============================================================
__device__ __forceinline__ void gemm_issue_copy(
    const float* __restrict__ Ap, const float* __restrict__ Bp,
    int kb, float* buf, int tid)
{
    const int r0 = tid >> 2;
    const int q0 = (tid & 3) * 4;
    cp16(buf + SMA + r0 * GS + q0, Ap + (size_t)r0 * DMODEL + kb + q0);
    cp16(buf + SMA + (r0 + 64) * GS + q0, Ap + (size_t)(r0 + 64) * DMODEL + kb + q0);
    cp16(buf + SMB + r0 * GS + q0, Bp + (size_t)r0 * DMODEL + kb + q0);
    asm volatile("cp.async.commit_group;" ::: "memory");
}

__device__ __forceinline__ void gemm_compute(
    const float* buf, float c[2][4][4], int wm, int wn, int lg, int lt)
{
    #pragma unroll
    for (int k0 = 0; k0 < 16; k0 += 8) {
        unsigned ah[2][4], al[2][4], bh[4][2], bl[4][2];
        #pragma unroll
        for (int mt = 0; mt < 2; mt++) {
            const int r = wm + mt * 16 + lg;
            splitu(buf[SMA + r * GS + k0 + lt],           ah[mt][0], al[mt][0]);
            splitu(buf[SMA + (r + 8) * GS + k0 + lt],     ah[mt][1], al[mt][1]);
            splitu(buf[SMA + r * GS + k0 + 4 + lt],       ah[mt][2], al[mt][2]);
            splitu(buf[SMA + (r + 8) * GS + k0 + 4 + lt], ah[mt][3], al[mt][3]);
        }
        #pragma unroll
        for (int nt = 0; nt < 4; nt++) {
            const int cc = wn + nt * 8 + lg;
            splitu(buf[SMB + cc * GS + k0 + lt],     bh[nt][0], bl[nt][0]);
            splitu(buf[SMB + cc * GS + k0 + 4 + lt], bh[nt][1], bl[nt][1]);
        }
        #pragma unroll
        for (int mt = 0; mt < 2; mt++)
            #pragma unroll
            for (int nt = 0; nt < 4; nt++) {
                mma_tf32(c[mt][nt], ah[mt], bh[nt]);
                mma_tf32(c[mt][nt], ah[mt], bl[nt]);
                mma_tf32(c[mt][nt], al[mt], bh[nt]);
            }
    }
}

__device__ __forceinline__ void mma_mainloop(
    const float* __restrict__ Ap, const float* __restrict__ Bp,
    float* sm, float c[2][4][4])
{
    const int tid = threadIdx.x;
    const int lane = tid & 31;
    const int wid = tid >> 5;
    const int wm = (wid & 3) * 32;
    const int wn = (wid >> 2) * 32;
    const int lg = lane >> 2;
    const int lt = lane & 3;
    const int NB = DMODEL / 16;

    gemm_issue_copy(Ap, Bp, 0, sm, tid);
    gemm_issue_copy(Ap, Bp, 16, sm + BUFSZ, tid);

    for (int i = 0; i < NB; i++) {
        if (i + 1 < NB)
            asm volatile("cp.async.wait_group 1;" ::: "memory");
        else
            asm volatile("cp.async.wait_group 0;" ::: "memory");
        __syncthreads();
        if (i + 2 < NB)
            gemm_issue_copy(Ap, Bp, (i + 2) * 16, sm + ((i + 2) % NSTAGE) * BUFSZ, tid);
        gemm_compute(sm + (i % NSTAGE) * BUFSZ, c, wm, wn, lg, lt);
    }
}

// ============================================================
// Kernel 1: QKV projection via 3xTF32 MMA (+RoPE epilogue)
// ============================================================
__global__ __launch_bounds__(256, 3) void qkv_mma_kernel(
    const float* __restrict__ x,
    const float* __restrict__ WQ,
    const float* __restrict__ WK,
    const float* __restrict__ WV)
{
    __shared__ float sm[SM_TOT];
    const int m0 = blockIdx.y * 128;
    const int e0 = blockIdx.x * 64;
    const int sect = e0 >> 10;
    const float* Wp = (sect == 0 ? WQ : (sect == 1 ? WK : WV)) + (size_t)(e0 & 1023) * DMODEL;
    const float* Ap = x + (size_t)m0 * DMODEL;

    float c[2][4][4] = {};
    mma_mainloop(Ap, Wp, sm, c);

    const int lane = threadIdx.x & 31;
    const int wid = threadIdx.x >> 5;
    const int wm = (wid & 3) * 32;
    const int wn = (wid >> 2) * 32;
    const int lg = lane >> 2, lt = lane & 3;
    float* dst = (sect == 0) ? g_Q : ((sect == 1) ? g_K : g_V);

    #pragma unroll
    for (int mt = 0; mt < 2; mt++) {
        #pragma unroll
        for (int nt = 0; nt < 4; nt++) {
            const int col = e0 + wn + nt * 8 + 2 * lt;
            const int ec = col & 1023;
            const int h = ec >> 6;
            const int d = ec & 63;
            #pragma unroll
            for (int half = 0; half < 2; half++) {
                const int row = m0 + wm + mt * 16 + lg + half * 8;
                const float v0 = c[mt][nt][half * 2 + 0];
                const float v1 = c[mt][nt][half * 2 + 1];
                const int b = row >> 11;
                const int srow = row & (SEQ - 1);
                const size_t oidx = (((size_t)(b * NHEAD + h)) * SEQ + srow) * DK + d;
                float2 o;
                if (sect < 2) {
                    const float cs = g_cos[srow * DK + d];
                    const float sn = g_sin[srow * DK + d];
                    o.x = v0 * cs - v1 * sn;
                    o.y = v1 * cs + v0 * sn;
                } else {
                    o.x = v0; o.y = v1;
                }
                *(float2*)(dst + oidx) = o;
            }
        }
    }
}

// ============================================================
// Kernel 3: output projection via 3xTF32 MMA
// ============================================================
__global__ __launch_bounds__(256, 3) void out_mma_kernel(
    const float* __restrict__ WO, float* __restrict__ out)
{
    __shared__ float sm[SM_TOT];
    const int m0 = blockIdx.y * 128;
    const int e0 = blockIdx.x * 64;
    const float* Ap = g_attn + (size_t)m0 * DMODEL;
    const float* Wp = WO + (size_t)e0 * DMODEL;

    float c[2][4][4] = {};
    mma_mainloop(Ap, Wp, sm, c);

    const int lane = threadIdx.x & 31;
    const int wid = threadIdx.x >> 5;
    const int wm = (wid & 3) * 32;
    const int wn = (wid >> 2) * 32;
    const int lg = lane >> 2, lt = lane & 3;

    #pragma unroll
    for (int mt = 0; mt < 2; mt++) {
        #pragma unroll
        for (int nt = 0; nt < 4; nt++) {
            const int col = e0 + wn + nt * 8 + 2 * lt;
            #pragma unroll
            for (int half = 0; half < 2; half++) {
                const int row = m0 + wm + mt * 16 + lg + half * 8;
                float2 o;
                o.x = c[mt][nt][half * 2 + 0];
                o.y = c[mt][nt][half * 2 + 1];
                *(float2*)(out + (size_t)row * DMODEL + col) = o;
            }
        }
    }
}

// ============================================================
// Kernel 2: causal flash attention — identical numerics to round 12;
// smem switched to DYNAMIC so >1 CTA/SM can reside (228KB carveout).
// ============================================================
#define KSTR 68
#define VSTR 72
#define PST  36
#define KVSTAGE (32*KSTR + 32*VSTR)   // 4480 floats per stage
#define ATTN_SMEM_BYTES ((2*KVSTAGE + 64*PST) * 4)   // 45056 B

__global__ __launch_bounds__(128, 3) void attn_mma_kernel()
{
    extern __shared__ float smem[];
    float* s_ps = smem + 2 * KVSTAGE;

    const int qt = gridDim.x - 1 - blockIdx.x;   // LPT: heavy tiles first
    const int bh = blockIdx.y;
    const int tid = threadIdx.x;
    const int w = tid >> 5;
    const int lane = tid & 31;
    const int lg = lane >> 2, lt = lane & 3;
    const int q0 = qt * 64;

    const float* Qb = g_Q + (size_t)bh * SEQ * DK;
    const float* Kb = g_K + (size_t)bh * SEQ * DK;
    const float* Vb = g_V + (size_t)bh * SEQ * DK;

    // ---- stage Q (pre-scaled 1/8) through stage-0 buffer ----
    {
        const int row = tid & 63, half = tid >> 6;
        const float* src = Qb + (size_t)(q0 + row) * DK + 32 * half;
        float* dq = smem + row * KSTR + 32 * half;
        #pragma unroll
        for (int i = 0; i < 8; i++) {
            float4 v = *(const float4*)(src + 4 * i);
            v.x *= 0.125f; v.y *= 0.125f; v.z *= 0.125f; v.w *= 0.125f;
            *(float4*)(dq + 4 * i) = v;
        }
    }
    __syncthreads();

    // ---- extract Q A-fragments (hi/lo, truncation split) ----
    unsigned qh[8][4], ql[8][4];
    {
        const int r0 = 16 * w + lg;
        #pragma unroll
        for (int kc = 0; kc < 8; kc++) {
            float f[4];
            f[0] = smem[r0 * KSTR + kc * 8 + lt];
            f[1] = smem[(r0 + 8) * KSTR + kc * 8 + lt];
            f[2] = smem[r0 * KSTR + kc * 8 + 4 + lt];
            f[3] = smem[(r0 + 8) * KSTR + kc * 8 + 4 + lt];
            #pragma unroll
            for (int i = 0; i < 4; i++) splitu(f[i], qh[kc][i], ql[kc][i]);
        }
    }
    __syncthreads();   // all warps done with Q staging before cp.async overwrites

    float o[8][4];
    #pragma unroll
    for (int nt = 0; nt < 8; nt++)
        #pragma unroll
        for (int i = 0; i < 4; i++) o[nt][i] = 0.f;
    float m0 = -1e30f, m1 = -1e30f, l0 = 0.f, l1 = 0.f;
    const int rg0 = q0 + 16 * w + lg;
    const int rg1 = rg0 + 8;
    const int nsub = 2 * qt + 2;

    // issue subtile 0
    {
        #pragma unroll
        for (int j = 0; j < 4; j++) {
            const int f = tid + j * 128;          // float4 index 0..511
            const int row = f >> 4, c4 = (f & 15) * 4;
            cp16(smem + row * KSTR + c4, Kb + (size_t)row * DK + c4);
            cp16(smem + 32 * KSTR + row * VSTR + c4, Vb + (size_t)row * DK + c4);
        }
        asm volatile("cp.async.commit_group;" ::: "memory");
    }

    for (int s32 = 0; s32 < nsub; s32++) {
        if (s32 + 1 < nsub) {
            const int k32n = (s32 + 1) * 32;
            float* buf = smem + ((s32 + 1) & 1) * KVSTAGE;
            #pragma unroll
            for (int j = 0; j < 4; j++) {
                const int f = tid + j * 128;
                const int row = f >> 4, c4 = (f & 15) * 4;
                cp16(buf + row * KSTR + c4, Kb + (size_t)(k32n + row) * DK + c4);
                cp16(buf + 32 * KSTR + row * VSTR + c4, Vb + (size_t)(k32n + row) * DK + c4);
            }
            asm volatile("cp.async.commit_group;" ::: "memory");
            asm volatile("cp.async.wait_group 1;" ::: "memory");
        } else {
            asm volatile("cp.async.wait_group 0;" ::: "memory");
        }
        __syncthreads();

        const int k32 = s32 * 32;
        const float* kb = smem + (s32 & 1) * KVSTAGE;
        const float* vb = kb + 32 * KSTR;
        const bool active = (k32 <= q0 + 16 * w + 15);
        if (active) {
            // ---- S = Q*K^T (3xTF32, K split at fragment load) ----
            float s[4][4];
            #pragma unroll
            for (int nt = 0; nt < 4; nt++)
                #pragma unroll
                for (int i = 0; i < 4; i++) s[nt][i] = 0.f;
            #pragma unroll
            for (int nt = 0; nt < 4; nt++) {
                const int kr = (nt * 8 + lg) * KSTR;
                #pragma unroll
                for (int kc = 0; kc < 8; kc++) {
                    unsigned bhf[2], blf[2];
                    splitu(kb[kr + kc * 8 + lt],     bhf[0], blf[0]);
                    splitu(kb[kr + kc * 8 + 4 + lt], bhf[1], blf[1]);
                    mma_tf32(s[nt], qh[kc], bhf);
                    mma_tf32(s[nt], ql[kc], bhf);
                    mma_tf32(s[nt], qh[kc], blf);
                }
            }
            // ---- causal mask ----
            if (k32 + 31 > rg0) {
                #pragma unroll
                for (int nt = 0; nt < 4; nt++) {
                    const int j = k32 + nt * 8 + 2 * lt;
                    if (j > rg0)     s[nt][0] = -1e30f;
                    if (j + 1 > rg0) s[nt][1] = -1e30f;
                }
            }
            if (k32 + 31 > rg1) {
                #pragma unroll
                for (int nt = 0; nt < 4; nt++) {
                    const int j = k32 + nt * 8 + 2 * lt;
                    if (j > rg1)     s[nt][2] = -1e30f;
                    if (j + 1 > rg1) s[nt][3] = -1e30f;
                }
            }
            // ---- online softmax ----
            float mt0 = -1e30f, mt1 = -1e30f;
            #pragma unroll
            for (int nt = 0; nt < 4; nt++) {
                mt0 = fmaxf(mt0, fmaxf(s[nt][0], s[nt][1]));
                mt1 = fmaxf(mt1, fmaxf(s[nt][2], s[nt][3]));
            }
            mt0 = fmaxf(mt0, __shfl_xor_sync(0xffffffffu, mt0, 1));
            mt0 = fmaxf(mt0, __shfl_xor_sync(0xffffffffu, mt0, 2));
            mt1 = fmaxf(mt1, __shfl_xor_sync(0xffffffffu, mt1, 1));
            mt1 = fmaxf(mt1, __shfl_xor_sync(0xffffffffu, mt1, 2));
            const float mn0 = fmaxf(m0, mt0), mn1 = fmaxf(m1, mt1);
            const float a0 = __expf(m0 - mn0), a1 = __expf(m1 - mn1);
            m0 = mn0; m1 = mn1;
            float sum0 = 0.f, sum1 = 0.f;
            #pragma unroll
            for (int nt = 0; nt < 4; nt++) {
                s[nt][0] = __expf(s[nt][0] - mn0);
                s[nt][1] = __expf(s[nt][1] - mn0);
                s[nt][2] = __expf(s[nt][2] - mn1);
                s[nt][3] = __expf(s[nt][3] - mn1);
                sum0 += s[nt][0] + s[nt][1];
                sum1 += s[nt][2] + s[nt][3];
            }
            sum0 += __shfl_xor_sync(0xffffffffu, sum0, 1);
            sum0 += __shfl_xor_sync(0xffffffffu, sum0, 2);
            sum1 += __shfl_xor_sync(0xffffffffu, sum1, 1);
            sum1 += __shfl_xor_sync(0xffffffffu, sum1, 2);
            l0 = l0 * a0 + sum0;
            l1 = l1 * a1 + sum1;
            #pragma unroll
            for (int nt = 0; nt < 8; nt++) {
                o[nt][0] *= a0; o[nt][1] *= a0;
                o[nt][2] *= a1; o[nt][3] *= a1;
            }
            // ---- stage P (rna, hedged) to own warp's rows ----
            {
                const int pr0 = (16 * w + lg) * PST;
                const int pr1 = (16 * w + 8 + lg) * PST;
                #pragma unroll
                for (int nt = 0; nt < 4; nt++) {
                    float2 p01 = make_float2(tf32_rna(s[nt][0]), tf32_rna(s[nt][1]));
                    float2 p23 = make_float2(tf32_rna(s[nt][2]), tf32_rna(s[nt][3]));
                    *(float2*)(s_ps + pr0 + nt * 8 + 2 * lt) = p01;
                    *(float2*)(s_ps + pr1 + nt * 8 + 2 * lt) = p23;
                }
            }
            __syncwarp();
            // ---- PV: O += P * V (V raw, HW-truncated) ----
            unsigned pa[4][4];
            #pragma unroll
            for (int kc = 0; kc < 4; kc++) {
                pa[kc][0] = fu(s_ps[(16 * w + lg) * PST + kc * 8 + lt]);
                pa[kc][1] = fu(s_ps[(16 * w + 8 + lg) * PST + kc * 8 + lt]);
                pa[kc][2] = fu(s_ps[(16 * w + lg) * PST + kc * 8 + 4 + lt]);
                pa[kc][3] = fu(s_ps[(16 * w + 8 + lg) * PST + kc * 8 + 4 + lt]);
            }
            #pragma unroll
            for (int nt = 0; nt < 8; nt++) {
                #pragma unroll
                for (int kc = 0; kc < 4; kc++) {
                    unsigned vbf[2];
                    vbf[0] = fu(vb[(kc * 8 + lt) * VSTR + nt * 8 + lg]);
                    vbf[1] = fu(vb[(kc * 8 + 4 + lt) * VSTR + nt * 8 + lg]);
                    mma_tf32(o[nt], pa[kc], vbf);
                }
            }
        }
        __syncthreads();   // compute done before next iter's issue overwrites this stage
    }

    // ---- normalize + write ----
    const float inv0 = 1.0f / l0, inv1 = 1.0f / l1;
    const int b = bh >> 4, h = bh & 15;
    float* dst0 = g_attn + ((size_t)b * SEQ + rg0) * DMODEL + h * DK;
    float* dst1 = g_attn + ((size_t)b * SEQ + rg1) * DMODEL + h * DK;
    #pragma unroll
    for (int nt = 0; nt < 8; nt++) {
        *(float2*)(dst0 + nt * 8 + 2 * lt) = make_float2(o[nt][0] * inv0, o[nt][1] * inv0);
        *(float2*)(dst1 + nt * 8 + 2 * lt) = make_float2(o[nt][2] * inv1, o[nt][3] * inv1);
    }
}

// ============================================================
extern "C" void kernel_launch(void* const* d_in, const int* in_sizes, int n_in,
                              void* d_out, int out_size)
{
    const float* x  = (const float*)d_in[0];
    const float* WQ = (const float*)d_in[1];
    const float* WK = (const float*)d_in[2];
    const float* WV = (const float*)d_in[3];
    const float* WO = (const float*)d_in[4];
    const int*   tp = (const int*)d_in[5];
    float* out = (float*)d_out;

    // Opt-in dynamic smem for attention (idempotent; host-side attribute,
    // not a stream op -> graph-capture safe).
    cudaFuncSetAttribute(attn_mma_kernel,
                         cudaFuncAttributeMaxDynamicSharedMemorySize,
                         ATTN_SMEM_BYTES);

    rope_table_kernel<<<SEQ, DK>>>(tp);
    qkv_mma_kernel<<<dim3(3 * DMODEL / 64, BATCH * SEQ / 128), 256>>>(x, WQ, WK, WV);
    attn_mma_kernel<<<dim3(SEQ / 64, NBH), 128, ATTN_SMEM_BYTES>>>();
    out_mma_kernel<<<dim3(DMODEL / 64, BATCH * SEQ / 128), 256>>>(WO, out);
}